// round 5
// baseline (speedup 1.0000x reference)
#include <cuda_runtime.h>
#include <cstdint>

// NLinear: out[b,f,o] = sum_i x[b,f,i] * W[f,i,o] + bias[f,o]
// B=4096, F=64, DIN=DOUT=256, fp32 in/out.
//
// Round-4 bisect build: pure fp32 SIMT tiled GEMM. No tcgen05, no device
// globals, no pre-pass, no dynamic smem, no attribute calls. One kernel.

#define B_DIM    4096
#define F_DIM    64
#define DIN_DIM  256
#define DOUT_DIM 256

// CTA computes a 128(M) x 256(N) tile for one feature f.
// 256 threads; thread tile 16(M) x 8(N); K-panel = 16.
__global__ void __launch_bounds__(256, 1) nlinear_kernel(
    const float* __restrict__ x,
    const float* __restrict__ w,
    const float* __restrict__ bias,
    float* __restrict__ out)
{
    __shared__ float xs[16 * 132];   // transposed x tile: xs[k][r], padded rows
    __shared__ float ws[16 * 256];   // w tile: ws[k][o]

    const int tid   = threadIdx.x;
    const int mtile = blockIdx.x;   // 0..31
    const int f     = blockIdx.y;   // 0..63

    const int c0 = (tid & 31) * 8;   // 8 output cols
    const int r0 = (tid >> 5) * 16;  // 16 output rows

    float acc[16][8];
#pragma unroll
    for (int i = 0; i < 16; i++)
#pragma unroll
        for (int j = 0; j < 8; j++) acc[i][j] = 0.0f;

    const float* xb = x + (size_t)(mtile * 128) * (F_DIM * DIN_DIM) + (size_t)f * DIN_DIM;
    const float* wb = w + (size_t)f * (DIN_DIM * DOUT_DIM);

    for (int k0 = 0; k0 < DIN_DIM; k0 += 16) {
        // load x tile transposed: xs[k][r]  (each thread: 8 scalars)
#pragma unroll
        for (int it = 0; it < 8; it++) {
            const int i = it * 256 + tid;   // 0..2047
            const int r = i >> 4;           // 0..127
            const int k = i & 15;           // 0..15
            xs[k * 132 + r] = xb[(size_t)r * (F_DIM * DIN_DIM) + k0 + k];
        }
        // load w tile: ws[k][o] (fully coalesced, 256 floats per row)
#pragma unroll
        for (int k = 0; k < 16; k++)
            ws[k * 256 + tid] = wb[(size_t)(k0 + k) * DOUT_DIM + tid];
        __syncthreads();

#pragma unroll
        for (int kk = 0; kk < 16; kk++) {
            float wv[8];
#pragma unroll
            for (int j = 0; j < 2; j++) {
                float4 t = *(const float4*)&ws[kk * 256 + c0 + j * 4];
                wv[j * 4 + 0] = t.x; wv[j * 4 + 1] = t.y;
                wv[j * 4 + 2] = t.z; wv[j * 4 + 3] = t.w;
            }
            float xv[16];
#pragma unroll
            for (int i2 = 0; i2 < 4; i2++) {
                float4 t = *(const float4*)&xs[kk * 132 + r0 + i2 * 4];
                xv[i2 * 4 + 0] = t.x; xv[i2 * 4 + 1] = t.y;
                xv[i2 * 4 + 2] = t.z; xv[i2 * 4 + 3] = t.w;
            }
#pragma unroll
            for (int i = 0; i < 16; i++)
#pragma unroll
                for (int j = 0; j < 8; j++)
                    acc[i][j] = fmaf(xv[i], wv[j], acc[i][j]);
        }
        __syncthreads();
    }

    // epilogue: + bias, vectorized stores
    const float* brow = bias + (size_t)f * DOUT_DIM + c0;
    float bv[8];
#pragma unroll
    for (int j = 0; j < 8; j++) bv[j] = brow[j];

#pragma unroll
    for (int i = 0; i < 16; i++) {
        float* orow = out + (size_t)(mtile * 128 + r0 + i) * (F_DIM * DOUT_DIM)
                          + (size_t)f * DOUT_DIM + c0;
        float4 o0, o1;
        o0.x = acc[i][0] + bv[0];
        o0.y = acc[i][1] + bv[1];
        o0.z = acc[i][2] + bv[2];
        o0.w = acc[i][3] + bv[3];
        o1.x = acc[i][4] + bv[4];
        o1.y = acc[i][5] + bv[5];
        o1.z = acc[i][6] + bv[6];
        o1.w = acc[i][7] + bv[7];
        *(float4*)(orow + 0) = o0;
        *(float4*)(orow + 4) = o1;
    }
}

extern "C" void kernel_launch(void* const* d_in, const int* in_sizes, int n_in,
                              void* d_out, int out_size)
{
    // Positional per metadata order (x, weight, b), with size-based override
    // as a cross-check.
    const float* x = (n_in > 0) ? (const float*)d_in[0] : nullptr;
    const float* w = (n_in > 1) ? (const float*)d_in[1] : nullptr;
    const float* b = (n_in > 2) ? (const float*)d_in[2] : nullptr;
    for (int i = 0; i < n_in; i++) {
        if (in_sizes[i] == B_DIM * F_DIM * DIN_DIM)         x = (const float*)d_in[i];
        else if (in_sizes[i] == F_DIM * DIN_DIM * DOUT_DIM) w = (const float*)d_in[i];
        else if (in_sizes[i] == F_DIM * DOUT_DIM)           b = (const float*)d_in[i];
    }
    float* out = (float*)d_out;

    nlinear_kernel<<<dim3(B_DIM / 128, F_DIM), 256>>>(x, w, b, out);
}

// round 8
// speedup vs baseline: 1.7337x; 1.7337x over previous
#include <cuda_runtime.h>
#include <cuda_bf16.h>
#include <cstdint>

// NLinear: out[b,f,o] = sum_i x[b,f,i] * W[f,i,o] + bias[f,o]
// B=4096, F=64, DIN=DOUT=256, fp32 in/out.
//
// Round-5: warp-level tensor cores via mma.sync (bf16x3 emulated fp32).
// Plain-PTX features only (ldmatrix sm_75+, bf16 mma sm_80+) — works under
// the harness's non-arch-specific sm_103 target. No tcgen05, no device
// globals, no dynamic smem.

#define B_DIM  4096
#define F_DIM  64
#define DIN    256
#define DOUT   256
#define KP     16          // K panel
#define SA     24          // A smem row stride in bf16 (48B: ldmatrix conflict-free)
#define SB     264         // B smem row stride in bf16 (528B: ldmatrix conflict-free)

__device__ __forceinline__ uint32_t smem_u32(const void* p) {
    uint32_t a;
    asm("{ .reg .u64 t; cvta.to.shared.u64 t, %1; cvt.u32.u64 %0, t; }"
        : "=r"(a) : "l"(p));
    return a;
}

#define LDSM4(R, addr) \
    asm volatile("ldmatrix.sync.aligned.m8n8.x4.shared.b16 {%0,%1,%2,%3}, [%4];" \
                 : "=r"((R)[0]), "=r"((R)[1]), "=r"((R)[2]), "=r"((R)[3]) \
                 : "r"(addr))

#define LDSM4T(R, addr) \
    asm volatile("ldmatrix.sync.aligned.m8n8.x4.trans.shared.b16 {%0,%1,%2,%3}, [%4];" \
                 : "=r"((R)[0]), "=r"((R)[1]), "=r"((R)[2]), "=r"((R)[3]) \
                 : "r"(addr))

#define MMA16816(C, A, b0, b1) \
    asm volatile("mma.sync.aligned.m16n8k16.row.col.f32.bf16.bf16.f32 " \
                 "{%0,%1,%2,%3}, {%4,%5,%6,%7}, {%8,%9}, {%0,%1,%2,%3};" \
                 : "+f"((C)[0]), "+f"((C)[1]), "+f"((C)[2]), "+f"((C)[3]) \
                 : "r"((A)[0]), "r"((A)[1]), "r"((A)[2]), "r"((A)[3]), \
                   "r"(b0), "r"(b1))

__device__ __forceinline__ uint32_t pack_bf16x2(float a, float b) {
    __nv_bfloat162 p;
    p.x = __float2bfloat16_rn(a);
    p.y = __float2bfloat16_rn(b);
    return *(uint32_t*)&p;
}

// CTA: 128(M) x 256(N) tile for one feature f. 8 warps; warp tile 32x128.
__global__ void __launch_bounds__(256, 1) nlinear_mma_kernel(
    const float* __restrict__ x,
    const float* __restrict__ w,
    const float* __restrict__ bias,
    float* __restrict__ out)
{
    // hi/lo bf16 operand tiles
    __shared__ __align__(16) __nv_bfloat16 As[2][128 * SA];  // [ver][m][k]
    __shared__ __align__(16) __nv_bfloat16 Bs[2][KP * SB];   // [ver][k][n]
    __shared__ float sbias[DOUT];

    const int tid  = threadIdx.x;
    const int lane = tid & 31;
    const int wid  = tid >> 5;
    const int mtile = blockIdx.x;   // 0..31
    const int f     = blockIdx.y;   // 0..63

    const int warp_m = (wid & 3) * 32;    // 0,32,64,96
    const int warp_n = (wid >> 2) * 128;  // 0 or 128

    sbias[tid] = bias[f * DOUT + tid];

    float acc[2][16][4];
#pragma unroll
    for (int mt = 0; mt < 2; mt++)
#pragma unroll
        for (int nt = 0; nt < 16; nt++)
#pragma unroll
            for (int q = 0; q < 4; q++) acc[mt][nt][q] = 0.0f;

    const float* xb = x + (size_t)(mtile * 128) * (F_DIM * DIN) + (size_t)f * DIN;
    const float* wb = w + (size_t)f * (DIN * DOUT);

    // ldmatrix source addresses (byte, shared space)
    const uint32_t As_base = smem_u32(As);
    const uint32_t Bs_base = smem_u32(Bs);
    uint32_t a_addr[2];
#pragma unroll
    for (int mt = 0; mt < 2; mt++)
        a_addr[mt] = As_base +
            (uint32_t)(((warp_m + mt * 16 + (lane & 15)) * SA + (lane >> 4) * 8) * 2);
    const uint32_t a_ver = 128 * SA * 2;   // hi -> lo byte offset

    const uint32_t b_row = (lane & 7) + ((lane >> 3) & 1) * 8;   // k within panel
    const uint32_t b_col8 = (lane & 16) >> 1;                    // 0 or 8
    const uint32_t b_addr = Bs_base +
        (uint32_t)((b_row * SB + warp_n + b_col8) * 2);
    const uint32_t b_ver = KP * SB * 2;

    // load maps
    const int xr0 = tid >> 2;          // 0..63 (two passes of 64 rows)
    const int xc  = (tid & 3) * 4;     // float4 col within 16-k panel
    const int wk  = tid >> 4;          // 0..15 k-row
    const int wc  = (tid & 15) * 16;   // 16 floats per thread

    for (int k0 = 0; k0 < DIN; k0 += KP) {
        // ---- x tile: 128 x 16 fp32 -> bf16 hi/lo ----
#pragma unroll
        for (int p = 0; p < 2; p++) {
            const int r = p * 64 + xr0;
            float4 v = *(const float4*)(xb + (size_t)r * (F_DIM * DIN) + k0 + xc);
            __nv_bfloat16 h0 = __float2bfloat16_rn(v.x);
            __nv_bfloat16 h1 = __float2bfloat16_rn(v.y);
            __nv_bfloat16 h2 = __float2bfloat16_rn(v.z);
            __nv_bfloat16 h3 = __float2bfloat16_rn(v.w);
            uint32_t hu0 = pack_bf16x2(v.x, v.y);   // same as {h0,h1}
            uint32_t hu1 = pack_bf16x2(v.z, v.w);
            uint32_t lu0 = pack_bf16x2(v.x - __bfloat162float(h0),
                                       v.y - __bfloat162float(h1));
            uint32_t lu1 = pack_bf16x2(v.z - __bfloat162float(h2),
                                       v.w - __bfloat162float(h3));
            const int e = r * SA + xc;
            *(uint2*)&As[0][e] = make_uint2(hu0, hu1);
            *(uint2*)&As[1][e] = make_uint2(lu0, lu1);
        }

        // ---- W tile: 16 x 256 fp32 -> bf16 hi/lo ----
        {
            const float* wrow = wb + (size_t)(k0 + wk) * DOUT + wc;
            float4 v0 = *(const float4*)(wrow + 0);
            float4 v1 = *(const float4*)(wrow + 4);
            float4 v2 = *(const float4*)(wrow + 8);
            float4 v3 = *(const float4*)(wrow + 12);
            float vs[16] = {v0.x,v0.y,v0.z,v0.w, v1.x,v1.y,v1.z,v1.w,
                            v2.x,v2.y,v2.z,v2.w, v3.x,v3.y,v3.z,v3.w};
            uint32_t hu[8], lu[8];
#pragma unroll
            for (int j = 0; j < 8; j++) {
                float a = vs[2*j], b = vs[2*j+1];
                __nv_bfloat16 ha = __float2bfloat16_rn(a);
                __nv_bfloat16 hb = __float2bfloat16_rn(b);
                hu[j] = pack_bf16x2(a, b);
                lu[j] = pack_bf16x2(a - __bfloat162float(ha),
                                    b - __bfloat162float(hb));
            }
            const int e = wk * SB + wc;
            *(uint4*)&Bs[0][e]     = make_uint4(hu[0], hu[1], hu[2], hu[3]);
            *(uint4*)&Bs[0][e + 8] = make_uint4(hu[4], hu[5], hu[6], hu[7]);
            *(uint4*)&Bs[1][e]     = make_uint4(lu[0], lu[1], lu[2], lu[3]);
            *(uint4*)&Bs[1][e + 8] = make_uint4(lu[4], lu[5], lu[6], lu[7]);
        }
        __syncthreads();

        // ---- A fragments ----
        uint32_t Ah[2][4], Al[2][4];
#pragma unroll
        for (int mt = 0; mt < 2; mt++) {
            LDSM4(Ah[mt], a_addr[mt]);
            LDSM4(Al[mt], a_addr[mt] + a_ver);
        }

        // ---- B fragments + MMAs, 16 n8-tiles in chunks of 2 ----
#pragma unroll
        for (int nc = 0; nc < 8; nc++) {
            uint32_t Bh[4], Bl[4];
            const uint32_t ba = b_addr + nc * 16 * 2;   // +16 n cols
            LDSM4T(Bh, ba);
            LDSM4T(Bl, ba + b_ver);
#pragma unroll
            for (int mt = 0; mt < 2; mt++) {
#pragma unroll
                for (int nt = 0; nt < 2; nt++) {
                    float* c = acc[mt][nc * 2 + nt];
                    MMA16816(c, Ah[mt], Bh[2*nt], Bh[2*nt+1]);
                    MMA16816(c, Al[mt], Bh[2*nt], Bh[2*nt+1]);
                    MMA16816(c, Ah[mt], Bl[2*nt], Bl[2*nt+1]);
                }
            }
        }
        __syncthreads();
    }

    // ---- epilogue: +bias, float2 stores ----
    const int r_lane = lane >> 2;
    const int c_lane = (lane & 3) * 2;
#pragma unroll
    for (int mt = 0; mt < 2; mt++) {
#pragma unroll
        for (int nt = 0; nt < 16; nt++) {
            const int col = warp_n + nt * 8 + c_lane;
            const int row0 = mtile * 128 + warp_m + mt * 16 + r_lane;
            float* o0 = out + (size_t)row0 * (F_DIM * DOUT) + (size_t)f * DOUT + col;
            float2 v0 = make_float2(acc[mt][nt][0] + sbias[col],
                                    acc[mt][nt][1] + sbias[col + 1]);
            *(float2*)o0 = v0;
            float* o1 = o0 + 8 * (F_DIM * DOUT);
            float2 v1 = make_float2(acc[mt][nt][2] + sbias[col],
                                    acc[mt][nt][3] + sbias[col + 1]);
            *(float2*)o1 = v1;
        }
    }
}

extern "C" void kernel_launch(void* const* d_in, const int* in_sizes, int n_in,
                              void* d_out, int out_size)
{
    const float* x = (n_in > 0) ? (const float*)d_in[0] : nullptr;
    const float* w = (n_in > 1) ? (const float*)d_in[1] : nullptr;
    const float* b = (n_in > 2) ? (const float*)d_in[2] : nullptr;
    for (int i = 0; i < n_in; i++) {
        if (in_sizes[i] == B_DIM * F_DIM * DIN)         x = (const float*)d_in[i];
        else if (in_sizes[i] == F_DIM * DIN * DOUT)     w = (const float*)d_in[i];
        else if (in_sizes[i] == F_DIM * DOUT)           b = (const float*)d_in[i];
    }
    float* out = (float*)d_out;

    nlinear_mma_kernel<<<dim3(B_DIM / 128, F_DIM), 256>>>(x, w, b, out);
}

// round 9
// speedup vs baseline: 2.3933x; 1.3805x over previous
#include <cuda_runtime.h>
#include <cuda_bf16.h>
#include <cstdint>

// NLinear: out[b,f,o] = sum_i x[b,f,i] * W[f,i,o] + bias[f,o]
// B=4096, F=64, DIN=DOUT=256, fp32 in/out.
//
// Round-8: mma.sync bf16x3 + pre-converted W (device scratch) + cp.async
// double-buffered W tiles + register-prefetched x tiles.

#define B_DIM  4096
#define F_DIM  64
#define DIN    256
#define DOUT   256
#define KP     16          // K panel
#define SA     24          // A smem row stride (bf16): 48B rows, ldmatrix conflict-free
#define SB     264         // B smem row stride (bf16): 528B rows, ldmatrix conflict-free

// pre-split W, bf16 hi/lo, layout [f][i][o] (same as source W)
static __device__ __nv_bfloat16 g_wh[F_DIM * DIN * DOUT];
static __device__ __nv_bfloat16 g_wl[F_DIM * DIN * DOUT];

__device__ __forceinline__ uint32_t smem_u32(const void* p) {
    uint32_t a;
    asm("{ .reg .u64 t; cvta.to.shared.u64 t, %1; cvt.u32.u64 %0, t; }"
        : "=r"(a) : "l"(p));
    return a;
}

#define LDSM4(R, addr) \
    asm volatile("ldmatrix.sync.aligned.m8n8.x4.shared.b16 {%0,%1,%2,%3}, [%4];" \
                 : "=r"((R)[0]), "=r"((R)[1]), "=r"((R)[2]), "=r"((R)[3]) \
                 : "r"(addr))

#define LDSM4T(R, addr) \
    asm volatile("ldmatrix.sync.aligned.m8n8.x4.trans.shared.b16 {%0,%1,%2,%3}, [%4];" \
                 : "=r"((R)[0]), "=r"((R)[1]), "=r"((R)[2]), "=r"((R)[3]) \
                 : "r"(addr))

#define MMA16816(C, A, b0, b1) \
    asm volatile("mma.sync.aligned.m16n8k16.row.col.f32.bf16.bf16.f32 " \
                 "{%0,%1,%2,%3}, {%4,%5,%6,%7}, {%8,%9}, {%0,%1,%2,%3};" \
                 : "+f"((C)[0]), "+f"((C)[1]), "+f"((C)[2]), "+f"((C)[3]) \
                 : "r"((A)[0]), "r"((A)[1]), "r"((A)[2]), "r"((A)[3]), \
                   "r"(b0), "r"(b1))

#define CP_ASYNC16(dst, src) \
    asm volatile("cp.async.cg.shared.global [%0], [%1], 16;" :: "r"(dst), "l"(src))
#define CP_COMMIT() asm volatile("cp.async.commit_group;" ::: "memory")
#define CP_WAIT0()  asm volatile("cp.async.wait_group 0;" ::: "memory")

__device__ __forceinline__ uint32_t pack_bf16x2(float a, float b) {
    __nv_bfloat162 p;
    p.x = __float2bfloat16_rn(a);
    p.y = __float2bfloat16_rn(b);
    return *(uint32_t*)&p;
}

// ---------------- prepass: split W fp32 -> bf16 hi/lo (layout preserved) ----
__global__ void __launch_bounds__(256, 1) split_w_kernel(const float* __restrict__ w) {
    const size_t i = (size_t)blockIdx.x * 256 + threadIdx.x;   // float4 index
    float4 v = ((const float4*)w)[i];
    __nv_bfloat16 h0 = __float2bfloat16_rn(v.x);
    __nv_bfloat16 h1 = __float2bfloat16_rn(v.y);
    __nv_bfloat16 h2 = __float2bfloat16_rn(v.z);
    __nv_bfloat16 h3 = __float2bfloat16_rn(v.w);
    uint2 hv = make_uint2(pack_bf16x2(v.x, v.y), pack_bf16x2(v.z, v.w));
    uint2 lv = make_uint2(pack_bf16x2(v.x - __bfloat162float(h0),
                                      v.y - __bfloat162float(h1)),
                          pack_bf16x2(v.z - __bfloat162float(h2),
                                      v.w - __bfloat162float(h3)));
    ((uint2*)g_wh)[i] = hv;
    ((uint2*)g_wl)[i] = lv;
}

// ---------------- main kernel ----------------
// CTA: 128(M) x 256(N) for one f. 8 warps; warp tile 32x128.
__global__ void __launch_bounds__(256, 1) nlinear_mma_kernel(
    const float* __restrict__ x,
    const float* __restrict__ bias,
    float* __restrict__ out)
{
    __shared__ __align__(16) __nv_bfloat16 As[2][128 * SA];        // [hi/lo][m][k]
    __shared__ __align__(16) __nv_bfloat16 Bs[2][2][KP * SB];      // [stage][hi/lo][k][n]
    __shared__ float sbias[DOUT];

    const int tid  = threadIdx.x;
    const int lane = tid & 31;
    const int wid  = tid >> 5;
    const int mtile = blockIdx.x;
    const int f     = blockIdx.y;

    const int warp_m = (wid & 3) * 32;
    const int warp_n = (wid >> 2) * 128;

    sbias[tid] = bias[f * DOUT + tid];

    float acc[2][16][4];
#pragma unroll
    for (int mt = 0; mt < 2; mt++)
#pragma unroll
        for (int nt = 0; nt < 16; nt++)
#pragma unroll
            for (int q = 0; q < 4; q++) acc[mt][nt][q] = 0.0f;

    const float* xb = x + (size_t)(mtile * 128) * (F_DIM * DIN) + (size_t)f * DIN;
    const __nv_bfloat16* whb = g_wh + (size_t)f * (DIN * DOUT);
    const __nv_bfloat16* wlb = g_wl + (size_t)f * (DIN * DOUT);

    // ldmatrix addresses
    const uint32_t As_base = smem_u32(As);
    const uint32_t Bs_base = smem_u32(Bs);
    uint32_t a_addr[2];
#pragma unroll
    for (int mt = 0; mt < 2; mt++)
        a_addr[mt] = As_base +
            (uint32_t)(((warp_m + mt * 16 + (lane & 15)) * SA + (lane >> 4) * 8) * 2);
    const uint32_t a_ver = 128 * SA * 2;

    const uint32_t b_row  = (lane & 7) + ((lane >> 3) & 1) * 8;
    const uint32_t b_col8 = (lane & 16) >> 1;
    const uint32_t b_addr0 = Bs_base + (uint32_t)((b_row * SB + warp_n + b_col8) * 2);
    const uint32_t b_ver   = KP * SB * 2;        // hi->lo offset (bytes)
    const uint32_t b_stage = 2 * KP * SB * 2;    // stage offset (bytes)

    // load maps
    const int xr0 = tid >> 2;          // row (two passes of 64)
    const int xc  = (tid & 3) * 4;     // float col within panel
    // W cp.async map: 1024 16B-chunks per (stage): idx = it*256+tid
    //   ver = idx>>9, rem = idx&511, row = rem>>5, c16 = rem&31

    float4 nx[2];   // x prefetch regs

    // ---- prologue: panel 0 ----
    {
#pragma unroll
        for (int it = 0; it < 4; it++) {
            const int idx = it * 256 + tid;
            const int ver = idx >> 9;
            const int rem = idx & 511;
            const int row = rem >> 5;
            const int c16 = rem & 31;
            const __nv_bfloat16* src = (ver ? wlb : whb) + (size_t)row * DOUT + c16 * 8;
            const uint32_t dst = Bs_base +
                (uint32_t)((0 * 2 + ver) * (KP * SB) + row * SB + c16 * 8) * 2;
            CP_ASYNC16(dst, src);
        }
        CP_COMMIT();
#pragma unroll
        for (int p = 0; p < 2; p++) {
            const int r = p * 64 + xr0;
            nx[p] = *(const float4*)(xb + (size_t)r * (F_DIM * DIN) + xc);
        }
        // convert x -> As
#pragma unroll
        for (int p = 0; p < 2; p++) {
            const int r = p * 64 + xr0;
            float4 v = nx[p];
            __nv_bfloat16 h0 = __float2bfloat16_rn(v.x);
            __nv_bfloat16 h1 = __float2bfloat16_rn(v.y);
            __nv_bfloat16 h2 = __float2bfloat16_rn(v.z);
            __nv_bfloat16 h3 = __float2bfloat16_rn(v.w);
            const int e = r * SA + xc;
            *(uint2*)&As[0][e] = make_uint2(pack_bf16x2(v.x, v.y), pack_bf16x2(v.z, v.w));
            *(uint2*)&As[1][e] = make_uint2(
                pack_bf16x2(v.x - __bfloat162float(h0), v.y - __bfloat162float(h1)),
                pack_bf16x2(v.z - __bfloat162float(h2), v.w - __bfloat162float(h3)));
        }
        CP_WAIT0();
        __syncthreads();
    }

    for (int k0 = 0; k0 < DIN; k0 += KP) {
        const int stage = (k0 >> 4) & 1;
        const bool more = (k0 + KP) < DIN;

        // ---- prefetch panel k0+16 ----
        if (more) {
            const int nk = k0 + KP;
            const int nstage = stage ^ 1;
#pragma unroll
            for (int it = 0; it < 4; it++) {
                const int idx = it * 256 + tid;
                const int ver = idx >> 9;
                const int rem = idx & 511;
                const int row = rem >> 5;
                const int c16 = rem & 31;
                const __nv_bfloat16* src =
                    (ver ? wlb : whb) + (size_t)(nk + row) * DOUT + c16 * 8;
                const uint32_t dst = Bs_base +
                    (uint32_t)((nstage * 2 + ver) * (KP * SB) + row * SB + c16 * 8) * 2;
                CP_ASYNC16(dst, src);
            }
            CP_COMMIT();
#pragma unroll
            for (int p = 0; p < 2; p++) {
                const int r = p * 64 + xr0;
                nx[p] = *(const float4*)(xb + (size_t)r * (F_DIM * DIN) + nk + xc);
            }
        }

        // ---- MMAs for panel k0 ----
        uint32_t Ah[2][4], Al[2][4];
#pragma unroll
        for (int mt = 0; mt < 2; mt++) {
            LDSM4(Ah[mt], a_addr[mt]);
            LDSM4(Al[mt], a_addr[mt] + a_ver);
        }
        const uint32_t bbase = b_addr0 + stage * b_stage;
#pragma unroll
        for (int nc = 0; nc < 8; nc++) {
            uint32_t Bh[4], Bl[4];
            const uint32_t ba = bbase + nc * 16 * 2;
            LDSM4T(Bh, ba);
            LDSM4T(Bl, ba + b_ver);
#pragma unroll
            for (int mt = 0; mt < 2; mt++) {
#pragma unroll
                for (int nt = 0; nt < 2; nt++) {
                    float* c = acc[mt][nc * 2 + nt];
                    MMA16816(c, Ah[mt], Bh[2*nt], Bh[2*nt+1]);
                    MMA16816(c, Al[mt], Bh[2*nt], Bh[2*nt+1]);
                    MMA16816(c, Ah[mt], Bl[2*nt], Bl[2*nt+1]);
                }
            }
        }
        __syncthreads();   // As consumed

        if (more) {
            // convert x regs -> As
#pragma unroll
            for (int p = 0; p < 2; p++) {
                const int r = p * 64 + xr0;
                float4 v = nx[p];
                __nv_bfloat16 h0 = __float2bfloat16_rn(v.x);
                __nv_bfloat16 h1 = __float2bfloat16_rn(v.y);
                __nv_bfloat16 h2 = __float2bfloat16_rn(v.z);
                __nv_bfloat16 h3 = __float2bfloat16_rn(v.w);
                const int e = r * SA + xc;
                *(uint2*)&As[0][e] = make_uint2(pack_bf16x2(v.x, v.y),
                                                pack_bf16x2(v.z, v.w));
                *(uint2*)&As[1][e] = make_uint2(
                    pack_bf16x2(v.x - __bfloat162float(h0), v.y - __bfloat162float(h1)),
                    pack_bf16x2(v.z - __bfloat162float(h2), v.w - __bfloat162float(h3)));
            }
            CP_WAIT0();
            __syncthreads();
        }
    }

    // ---- epilogue ----
    const int r_lane = lane >> 2;
    const int c_lane = (lane & 3) * 2;
#pragma unroll
    for (int mt = 0; mt < 2; mt++) {
#pragma unroll
        for (int nt = 0; nt < 16; nt++) {
            const int col = warp_n + nt * 8 + c_lane;
            const int row0 = mtile * 128 + warp_m + mt * 16 + r_lane;
            float* o0 = out + (size_t)row0 * (F_DIM * DOUT) + (size_t)f * DOUT + col;
            *(float2*)o0 = make_float2(acc[mt][nt][0] + sbias[col],
                                       acc[mt][nt][1] + sbias[col + 1]);
            float* o1 = o0 + 8 * (F_DIM * DOUT);
            *(float2*)o1 = make_float2(acc[mt][nt][2] + sbias[col],
                                       acc[mt][nt][3] + sbias[col + 1]);
        }
    }
}

extern "C" void kernel_launch(void* const* d_in, const int* in_sizes, int n_in,
                              void* d_out, int out_size)
{
    const float* x = (n_in > 0) ? (const float*)d_in[0] : nullptr;
    const float* w = (n_in > 1) ? (const float*)d_in[1] : nullptr;
    const float* b = (n_in > 2) ? (const float*)d_in[2] : nullptr;
    for (int i = 0; i < n_in; i++) {
        if (in_sizes[i] == B_DIM * F_DIM * DIN)     x = (const float*)d_in[i];
        else if (in_sizes[i] == F_DIM * DIN * DOUT) w = (const float*)d_in[i];
        else if (in_sizes[i] == F_DIM * DOUT)       b = (const float*)d_in[i];
    }
    float* out = (float*)d_out;

    // prepass: 4,194,304 floats / 4 per thread / 256 threads = 4096 blocks
    split_w_kernel<<<4096, 256>>>(w);
    nlinear_mma_kernel<<<dim3(B_DIM / 128, F_DIM), 256>>>(x, b, out);
}

// round 10
// speedup vs baseline: 2.7010x; 1.1286x over previous
#include <cuda_runtime.h>
#include <cuda_bf16.h>
#include <cstdint>

// NLinear: out[b,f,o] = sum_i x[b,f,i] * W[f,i,o] + bias[f,o]
// B=4096, F=64, DIN=DOUT=256, fp32 in/out.
//
// Round-9: mma.sync bf16x3, pre-converted W, cp.async double-buffered W,
// register-prefetched x. NEW: 64Mx256N CTA + __launch_bounds__(256,2) so
// TWO CTAs fit per SM (register file was the occupancy cap at 238 regs).

#define B_DIM  4096
#define F_DIM  64
#define DIN    256
#define DOUT   256
#define KP     16          // K panel
#define MT     64          // CTA M tile
#define SA     24          // A smem row stride (bf16)
#define SB     264         // B smem row stride (bf16)

// pre-split W, bf16 hi/lo, layout [f][i][o]
static __device__ __nv_bfloat16 g_wh[F_DIM * DIN * DOUT];
static __device__ __nv_bfloat16 g_wl[F_DIM * DIN * DOUT];

__device__ __forceinline__ uint32_t smem_u32(const void* p) {
    uint32_t a;
    asm("{ .reg .u64 t; cvta.to.shared.u64 t, %1; cvt.u32.u64 %0, t; }"
        : "=r"(a) : "l"(p));
    return a;
}

#define LDSM4(R, addr) \
    asm volatile("ldmatrix.sync.aligned.m8n8.x4.shared.b16 {%0,%1,%2,%3}, [%4];" \
                 : "=r"((R)[0]), "=r"((R)[1]), "=r"((R)[2]), "=r"((R)[3]) \
                 : "r"(addr))

#define LDSM4T(R, addr) \
    asm volatile("ldmatrix.sync.aligned.m8n8.x4.trans.shared.b16 {%0,%1,%2,%3}, [%4];" \
                 : "=r"((R)[0]), "=r"((R)[1]), "=r"((R)[2]), "=r"((R)[3]) \
                 : "r"(addr))

#define MMA16816(C, A, b0, b1) \
    asm volatile("mma.sync.aligned.m16n8k16.row.col.f32.bf16.bf16.f32 " \
                 "{%0,%1,%2,%3}, {%4,%5,%6,%7}, {%8,%9}, {%0,%1,%2,%3};" \
                 : "+f"((C)[0]), "+f"((C)[1]), "+f"((C)[2]), "+f"((C)[3]) \
                 : "r"((A)[0]), "r"((A)[1]), "r"((A)[2]), "r"((A)[3]), \
                   "r"(b0), "r"(b1))

#define CP_ASYNC16(dst, src) \
    asm volatile("cp.async.cg.shared.global [%0], [%1], 16;" :: "r"(dst), "l"(src))
#define CP_COMMIT() asm volatile("cp.async.commit_group;" ::: "memory")
#define CP_WAIT0()  asm volatile("cp.async.wait_group 0;" ::: "memory")

__device__ __forceinline__ uint32_t pack_bf16x2(float a, float b) {
    __nv_bfloat162 p;
    p.x = __float2bfloat16_rn(a);
    p.y = __float2bfloat16_rn(b);
    return *(uint32_t*)&p;
}

// ---------------- prepass: split W fp32 -> bf16 hi/lo ----------------
__global__ void __launch_bounds__(256, 1) split_w_kernel(const float* __restrict__ w) {
    const size_t i = (size_t)blockIdx.x * 256 + threadIdx.x;   // float4 index
    float4 v = ((const float4*)w)[i];
    __nv_bfloat16 h0 = __float2bfloat16_rn(v.x);
    __nv_bfloat16 h1 = __float2bfloat16_rn(v.y);
    __nv_bfloat16 h2 = __float2bfloat16_rn(v.z);
    __nv_bfloat16 h3 = __float2bfloat16_rn(v.w);
    uint2 hv = make_uint2(pack_bf16x2(v.x, v.y), pack_bf16x2(v.z, v.w));
    uint2 lv = make_uint2(pack_bf16x2(v.x - __bfloat162float(h0),
                                      v.y - __bfloat162float(h1)),
                          pack_bf16x2(v.z - __bfloat162float(h2),
                                      v.w - __bfloat162float(h3)));
    ((uint2*)g_wh)[i] = hv;
    ((uint2*)g_wl)[i] = lv;
}

// ---------------- main kernel ----------------
// CTA: 64(M) x 256(N) for one f. 8 warps; warp tile 16x128. 2 CTAs/SM.
__global__ void __launch_bounds__(256, 2) nlinear_mma_kernel(
    const float* __restrict__ x,
    const float* __restrict__ bias,
    float* __restrict__ out)
{
    __shared__ __align__(16) __nv_bfloat16 As[2][MT * SA];        // [hi/lo][m][k]
    __shared__ __align__(16) __nv_bfloat16 Bs[2][2][KP * SB];     // [stage][hi/lo][k][n]
    __shared__ float sbias[DOUT];

    const int tid  = threadIdx.x;
    const int lane = tid & 31;
    const int wid  = tid >> 5;
    const int mtile = blockIdx.x;   // 0..63
    const int f     = blockIdx.y;   // 0..63

    const int warp_m = (wid & 3) * 16;    // 0,16,32,48
    const int warp_n = (wid >> 2) * 128;  // 0 or 128

    sbias[tid] = bias[f * DOUT + tid];

    float acc[16][4];
#pragma unroll
    for (int nt = 0; nt < 16; nt++)
#pragma unroll
        for (int q = 0; q < 4; q++) acc[nt][q] = 0.0f;

    const float* xb = x + (size_t)(mtile * MT) * (F_DIM * DIN) + (size_t)f * DIN;
    const __nv_bfloat16* whb = g_wh + (size_t)f * (DIN * DOUT);
    const __nv_bfloat16* wlb = g_wl + (size_t)f * (DIN * DOUT);

    // ldmatrix addresses
    const uint32_t As_base = smem_u32(As);
    const uint32_t Bs_base = smem_u32(Bs);
    const uint32_t a_addr = As_base +
        (uint32_t)(((warp_m + (lane & 15)) * SA + (lane >> 4) * 8) * 2);
    const uint32_t a_ver = MT * SA * 2;

    const uint32_t b_row  = (lane & 7) + ((lane >> 3) & 1) * 8;
    const uint32_t b_col8 = (lane & 16) >> 1;
    const uint32_t b_addr0 = Bs_base + (uint32_t)((b_row * SB + warp_n + b_col8) * 2);
    const uint32_t b_ver   = KP * SB * 2;
    const uint32_t b_stage = 2 * KP * SB * 2;

    // x load map: 64 rows x 4 float4 = 256 float4 -> one per thread
    const int xr = tid >> 2;
    const int xc = (tid & 3) * 4;

    float4 nx;

    // ---- prologue: panel 0 ----
    {
#pragma unroll
        for (int it = 0; it < 4; it++) {
            const int idx = it * 256 + tid;
            const int ver = idx >> 9;
            const int rem = idx & 511;
            const int row = rem >> 5;
            const int c16 = rem & 31;
            const __nv_bfloat16* src = (ver ? wlb : whb) + (size_t)row * DOUT + c16 * 8;
            const uint32_t dst = Bs_base +
                (uint32_t)((ver) * (KP * SB) + row * SB + c16 * 8) * 2;
            CP_ASYNC16(dst, src);
        }
        CP_COMMIT();
        nx = *(const float4*)(xb + (size_t)xr * (F_DIM * DIN) + xc);
        {
            float4 v = nx;
            __nv_bfloat16 h0 = __float2bfloat16_rn(v.x);
            __nv_bfloat16 h1 = __float2bfloat16_rn(v.y);
            __nv_bfloat16 h2 = __float2bfloat16_rn(v.z);
            __nv_bfloat16 h3 = __float2bfloat16_rn(v.w);
            const int e = xr * SA + xc;
            *(uint2*)&As[0][e] = make_uint2(pack_bf16x2(v.x, v.y), pack_bf16x2(v.z, v.w));
            *(uint2*)&As[1][e] = make_uint2(
                pack_bf16x2(v.x - __bfloat162float(h0), v.y - __bfloat162float(h1)),
                pack_bf16x2(v.z - __bfloat162float(h2), v.w - __bfloat162float(h3)));
        }
        CP_WAIT0();
        __syncthreads();
    }

    for (int k0 = 0; k0 < DIN; k0 += KP) {
        const int stage = (k0 >> 4) & 1;
        const bool more = (k0 + KP) < DIN;

        // ---- prefetch panel k0+16 ----
        if (more) {
            const int nk = k0 + KP;
            const int nstage = stage ^ 1;
#pragma unroll
            for (int it = 0; it < 4; it++) {
                const int idx = it * 256 + tid;
                const int ver = idx >> 9;
                const int rem = idx & 511;
                const int row = rem >> 5;
                const int c16 = rem & 31;
                const __nv_bfloat16* src =
                    (ver ? wlb : whb) + (size_t)(nk + row) * DOUT + c16 * 8;
                const uint32_t dst = Bs_base +
                    (uint32_t)((nstage * 2 + ver) * (KP * SB) + row * SB + c16 * 8) * 2;
                CP_ASYNC16(dst, src);
            }
            CP_COMMIT();
            nx = *(const float4*)(xb + (size_t)xr * (F_DIM * DIN) + nk + xc);
        }

        // ---- MMAs for panel k0 ----
        uint32_t Ah[4], Al[4];
        LDSM4(Ah, a_addr);
        LDSM4(Al, a_addr + a_ver);
        const uint32_t bbase = b_addr0 + stage * b_stage;
#pragma unroll
        for (int nc = 0; nc < 8; nc++) {
            uint32_t Bh[4], Bl[4];
            const uint32_t ba = bbase + nc * 16 * 2;
            LDSM4T(Bh, ba);
            LDSM4T(Bl, ba + b_ver);
#pragma unroll
            for (int nt = 0; nt < 2; nt++) {
                float* c = acc[nc * 2 + nt];
                MMA16816(c, Ah, Bh[2*nt], Bh[2*nt+1]);
                MMA16816(c, Al, Bh[2*nt], Bh[2*nt+1]);
                MMA16816(c, Ah, Bl[2*nt], Bl[2*nt+1]);
            }
        }
        __syncthreads();   // As + Bs stage consumed

        if (more) {
            float4 v = nx;
            __nv_bfloat16 h0 = __float2bfloat16_rn(v.x);
            __nv_bfloat16 h1 = __float2bfloat16_rn(v.y);
            __nv_bfloat16 h2 = __float2bfloat16_rn(v.z);
            __nv_bfloat16 h3 = __float2bfloat16_rn(v.w);
            const int e = xr * SA + xc;
            *(uint2*)&As[0][e] = make_uint2(pack_bf16x2(v.x, v.y), pack_bf16x2(v.z, v.w));
            *(uint2*)&As[1][e] = make_uint2(
                pack_bf16x2(v.x - __bfloat162float(h0), v.y - __bfloat162float(h1)),
                pack_bf16x2(v.z - __bfloat162float(h2), v.w - __bfloat162float(h3)));
            CP_WAIT0();
            __syncthreads();
        }
    }

    // ---- epilogue ----
    const int r_lane = lane >> 2;
    const int c_lane = (lane & 3) * 2;
#pragma unroll
    for (int nt = 0; nt < 16; nt++) {
        const int col = warp_n + nt * 8 + c_lane;
        const int row0 = mtile * MT + warp_m + r_lane;
        float* o0 = out + (size_t)row0 * (F_DIM * DOUT) + (size_t)f * DOUT + col;
        *(float2*)o0 = make_float2(acc[nt][0] + sbias[col],
                                   acc[nt][1] + sbias[col + 1]);
        float* o1 = o0 + 8 * (F_DIM * DOUT);
        *(float2*)o1 = make_float2(acc[nt][2] + sbias[col],
                                   acc[nt][3] + sbias[col + 1]);
    }
}

extern "C" void kernel_launch(void* const* d_in, const int* in_sizes, int n_in,
                              void* d_out, int out_size)
{
    const float* x = (n_in > 0) ? (const float*)d_in[0] : nullptr;
    const float* w = (n_in > 1) ? (const float*)d_in[1] : nullptr;
    const float* b = (n_in > 2) ? (const float*)d_in[2] : nullptr;
    for (int i = 0; i < n_in; i++) {
        if (in_sizes[i] == B_DIM * F_DIM * DIN)     x = (const float*)d_in[i];
        else if (in_sizes[i] == F_DIM * DIN * DOUT) w = (const float*)d_in[i];
        else if (in_sizes[i] == F_DIM * DOUT)       b = (const float*)d_in[i];
    }
    float* out = (float*)d_out;

    split_w_kernel<<<4096, 256>>>(w);
    nlinear_mma_kernel<<<dim3(B_DIM / MT, F_DIM), 256>>>(x, b, out);
}

// round 11
// speedup vs baseline: 3.6985x; 1.3693x over previous
#include <cuda_runtime.h>
#include <cuda_fp16.h>
#include <cstdint>

// NLinear: out[b,f,o] = sum_i x[b,f,i] * W[f,i,o] + bias[f,o]
// B=4096, F=64, DIN=DOUT=256, fp32 in/out.
//
// Round-10: SINGLE-PASS fp16 mma.sync (e5m10 quantization error ~4e-4 < 1e-3
// threshold). 3x less tensor work than bf16x3. Pre-converted W (fp16 device
// scratch), cp.async double-buffered W, register-prefetched x, 64Mx256N CTA,
// 2 CTAs/SM.

#define B_DIM  4096
#define F_DIM  64
#define DIN    256
#define DOUT   256
#define KP     16          // K panel
#define MT     64          // CTA M tile
#define SA     24          // A smem row stride (fp16)
#define SB     264         // B smem row stride (fp16)

// pre-converted W, fp16, layout [f][i][o]
static __device__ __half g_wh[F_DIM * DIN * DOUT];

__device__ __forceinline__ uint32_t smem_u32(const void* p) {
    uint32_t a;
    asm("{ .reg .u64 t; cvta.to.shared.u64 t, %1; cvt.u32.u64 %0, t; }"
        : "=r"(a) : "l"(p));
    return a;
}

#define LDSM4(R, addr) \
    asm volatile("ldmatrix.sync.aligned.m8n8.x4.shared.b16 {%0,%1,%2,%3}, [%4];" \
                 : "=r"((R)[0]), "=r"((R)[1]), "=r"((R)[2]), "=r"((R)[3]) \
                 : "r"(addr))

#define LDSM4T(R, addr) \
    asm volatile("ldmatrix.sync.aligned.m8n8.x4.trans.shared.b16 {%0,%1,%2,%3}, [%4];" \
                 : "=r"((R)[0]), "=r"((R)[1]), "=r"((R)[2]), "=r"((R)[3]) \
                 : "r"(addr))

#define MMA16816F16(C, A, b0, b1) \
    asm volatile("mma.sync.aligned.m16n8k16.row.col.f32.f16.f16.f32 " \
                 "{%0,%1,%2,%3}, {%4,%5,%6,%7}, {%8,%9}, {%0,%1,%2,%3};" \
                 : "+f"((C)[0]), "+f"((C)[1]), "+f"((C)[2]), "+f"((C)[3]) \
                 : "r"((A)[0]), "r"((A)[1]), "r"((A)[2]), "r"((A)[3]), \
                   "r"(b0), "r"(b1))

#define CP_ASYNC16(dst, src) \
    asm volatile("cp.async.cg.shared.global [%0], [%1], 16;" :: "r"(dst), "l"(src))
#define CP_COMMIT() asm volatile("cp.async.commit_group;" ::: "memory")
#define CP_WAIT0()  asm volatile("cp.async.wait_group 0;" ::: "memory")

__device__ __forceinline__ uint32_t pack_h2(float a, float b) {
    __half2 p;
    p.x = __float2half_rn(a);
    p.y = __float2half_rn(b);
    return *(uint32_t*)&p;
}

// ---------------- prepass: W fp32 -> fp16 ----------------
__global__ void __launch_bounds__(256, 1) conv_w_kernel(const float* __restrict__ w) {
    const size_t i = (size_t)blockIdx.x * 256 + threadIdx.x;   // float4 index
    float4 v = ((const float4*)w)[i];
    ((uint2*)g_wh)[i] = make_uint2(pack_h2(v.x, v.y), pack_h2(v.z, v.w));
}

// ---------------- main kernel ----------------
// CTA: 64(M) x 256(N) for one f. 8 warps; warp tile 16x128. 2 CTAs/SM.
__global__ void __launch_bounds__(256, 2) nlinear_mma_kernel(
    const float* __restrict__ x,
    const float* __restrict__ bias,
    float* __restrict__ out)
{
    __shared__ __align__(16) __half As[MT * SA];           // [m][k]
    __shared__ __align__(16) __half Bs[2][KP * SB];        // [stage][k][n]
    __shared__ float sbias[DOUT];

    const int tid  = threadIdx.x;
    const int lane = tid & 31;
    const int wid  = tid >> 5;
    const int mtile = blockIdx.x;   // 0..63
    const int f     = blockIdx.y;   // 0..63

    const int warp_m = (wid & 3) * 16;    // 0,16,32,48
    const int warp_n = (wid >> 2) * 128;  // 0 or 128

    sbias[tid] = bias[f * DOUT + tid];

    float acc[16][4];
#pragma unroll
    for (int nt = 0; nt < 16; nt++)
#pragma unroll
        for (int q = 0; q < 4; q++) acc[nt][q] = 0.0f;

    const float* xb = x + (size_t)(mtile * MT) * (F_DIM * DIN) + (size_t)f * DIN;
    const __half* whb = g_wh + (size_t)f * (DIN * DOUT);

    // ldmatrix addresses
    const uint32_t As_base = smem_u32(As);
    const uint32_t Bs_base = smem_u32(Bs);
    const uint32_t a_addr = As_base +
        (uint32_t)(((warp_m + (lane & 15)) * SA + (lane >> 4) * 8) * 2);

    const uint32_t b_row  = (lane & 7) + ((lane >> 3) & 1) * 8;
    const uint32_t b_col8 = (lane & 16) >> 1;
    const uint32_t b_addr0 = Bs_base + (uint32_t)((b_row * SB + warp_n + b_col8) * 2);
    const uint32_t b_stage = KP * SB * 2;   // stage offset (bytes)

    // x load map: 64 rows x 4 float4 -> one per thread
    const int xr = tid >> 2;
    const int xc = (tid & 3) * 4;

    // W cp.async map per stage: 512 16B-chunks: idx = it*256+tid (it<2)
    //   row = idx>>5 (0..15), c16 = idx&31
    float4 nx;

    // ---- prologue: panel 0 ----
    {
#pragma unroll
        for (int it = 0; it < 2; it++) {
            const int idx = it * 256 + tid;
            const int row = idx >> 5;
            const int c16 = idx & 31;
            const __half* src = whb + (size_t)row * DOUT + c16 * 8;
            const uint32_t dst = Bs_base + (uint32_t)(row * SB + c16 * 8) * 2;
            CP_ASYNC16(dst, src);
        }
        CP_COMMIT();
        nx = *(const float4*)(xb + (size_t)xr * (F_DIM * DIN) + xc);
        *(uint2*)&As[xr * SA + xc] =
            make_uint2(pack_h2(nx.x, nx.y), pack_h2(nx.z, nx.w));
        CP_WAIT0();
        __syncthreads();
    }

    for (int k0 = 0; k0 < DIN; k0 += KP) {
        const int stage = (k0 >> 4) & 1;
        const bool more = (k0 + KP) < DIN;

        // ---- prefetch panel k0+16 ----
        if (more) {
            const int nk = k0 + KP;
            const int nstage = stage ^ 1;
#pragma unroll
            for (int it = 0; it < 2; it++) {
                const int idx = it * 256 + tid;
                const int row = idx >> 5;
                const int c16 = idx & 31;
                const __half* src = whb + (size_t)(nk + row) * DOUT + c16 * 8;
                const uint32_t dst = Bs_base +
                    (uint32_t)(nstage * (KP * SB) + row * SB + c16 * 8) * 2;
                CP_ASYNC16(dst, src);
            }
            CP_COMMIT();
            nx = *(const float4*)(xb + (size_t)xr * (F_DIM * DIN) + nk + xc);
        }

        // ---- MMAs for panel k0 ----
        uint32_t Ah[4];
        LDSM4(Ah, a_addr);
        const uint32_t bbase = b_addr0 + stage * b_stage;
#pragma unroll
        for (int nc = 0; nc < 8; nc++) {
            uint32_t Bh[4];
            LDSM4T(Bh, bbase + nc * 16 * 2);
#pragma unroll
            for (int nt = 0; nt < 2; nt++) {
                float* c = acc[nc * 2 + nt];
                MMA16816F16(c, Ah, Bh[2*nt], Bh[2*nt+1]);
            }
        }
        __syncthreads();   // As + Bs stage consumed

        if (more) {
            *(uint2*)&As[xr * SA + xc] =
                make_uint2(pack_h2(nx.x, nx.y), pack_h2(nx.z, nx.w));
            CP_WAIT0();
            __syncthreads();
        }
    }

    // ---- epilogue ----
    const int r_lane = lane >> 2;
    const int c_lane = (lane & 3) * 2;
#pragma unroll
    for (int nt = 0; nt < 16; nt++) {
        const int col = warp_n + nt * 8 + c_lane;
        const int row0 = mtile * MT + warp_m + r_lane;
        float* o0 = out + (size_t)row0 * (F_DIM * DOUT) + (size_t)f * DOUT + col;
        *(float2*)o0 = make_float2(acc[nt][0] + sbias[col],
                                   acc[nt][1] + sbias[col + 1]);
        float* o1 = o0 + 8 * (F_DIM * DOUT);
        *(float2*)o1 = make_float2(acc[nt][2] + sbias[col],
                                   acc[nt][3] + sbias[col + 1]);
    }
}

extern "C" void kernel_launch(void* const* d_in, const int* in_sizes, int n_in,
                              void* d_out, int out_size)
{
    const float* x = (n_in > 0) ? (const float*)d_in[0] : nullptr;
    const float* w = (n_in > 1) ? (const float*)d_in[1] : nullptr;
    const float* b = (n_in > 2) ? (const float*)d_in[2] : nullptr;
    for (int i = 0; i < n_in; i++) {
        if (in_sizes[i] == B_DIM * F_DIM * DIN)     x = (const float*)d_in[i];
        else if (in_sizes[i] == F_DIM * DIN * DOUT) w = (const float*)d_in[i];
        else if (in_sizes[i] == F_DIM * DOUT)       b = (const float*)d_in[i];
    }
    float* out = (float*)d_out;

    conv_w_kernel<<<4096, 256>>>(w);
    nlinear_mma_kernel<<<dim3(B_DIM / MT, F_DIM), 256>>>(x, b, out);
}

// round 12
// speedup vs baseline: 4.7099x; 1.2735x over previous
#include <cuda_runtime.h>
#include <cuda_fp16.h>
#include <cstdint>

// NLinear: out[b,f,o] = sum_i x[b,f,i] * W[f,i,o] + bias[f,o]
// B=4096, F=64, DIN=DOUT=256, fp32 in/out.
//
// Round-11: fp16 mma.sync, pre-converted W, cp.async W stages.
// NEW: KP=32 (8 panels), double-buffered As AND Bs -> ONE barrier per panel,
// longer MMA runs to cover the distance-1 x prefetch from DRAM.

#define B_DIM  4096
#define F_DIM  64
#define DIN    256
#define DOUT   256
#define KP     32          // K panel
#define MT     64          // CTA M tile
#define SA     40          // As row stride (fp16): 80B rows, ldmatrix conflict-free
#define SB     264         // Bs row stride (fp16): 528B rows, ldmatrix conflict-free

// pre-converted W, fp16, layout [f][i][o]
static __device__ __half g_wh[F_DIM * DIN * DOUT];

__device__ __forceinline__ uint32_t smem_u32(const void* p) {
    uint32_t a;
    asm("{ .reg .u64 t; cvta.to.shared.u64 t, %1; cvt.u32.u64 %0, t; }"
        : "=r"(a) : "l"(p));
    return a;
}

#define LDSM4(R, addr) \
    asm volatile("ldmatrix.sync.aligned.m8n8.x4.shared.b16 {%0,%1,%2,%3}, [%4];" \
                 : "=r"((R)[0]), "=r"((R)[1]), "=r"((R)[2]), "=r"((R)[3]) \
                 : "r"(addr))

#define LDSM4T(R, addr) \
    asm volatile("ldmatrix.sync.aligned.m8n8.x4.trans.shared.b16 {%0,%1,%2,%3}, [%4];" \
                 : "=r"((R)[0]), "=r"((R)[1]), "=r"((R)[2]), "=r"((R)[3]) \
                 : "r"(addr))

#define MMA16816F16(C, A, b0, b1) \
    asm volatile("mma.sync.aligned.m16n8k16.row.col.f32.f16.f16.f32 " \
                 "{%0,%1,%2,%3}, {%4,%5,%6,%7}, {%8,%9}, {%0,%1,%2,%3};" \
                 : "+f"((C)[0]), "+f"((C)[1]), "+f"((C)[2]), "+f"((C)[3]) \
                 : "r"((A)[0]), "r"((A)[1]), "r"((A)[2]), "r"((A)[3]), \
                   "r"(b0), "r"(b1))

#define CP_ASYNC16(dst, src) \
    asm volatile("cp.async.cg.shared.global [%0], [%1], 16;" :: "r"(dst), "l"(src))
#define CP_COMMIT() asm volatile("cp.async.commit_group;" ::: "memory")
#define CP_WAIT0()  asm volatile("cp.async.wait_group 0;" ::: "memory")

__device__ __forceinline__ uint32_t pack_h2(float a, float b) {
    __half2 p;
    p.x = __float2half_rn(a);
    p.y = __float2half_rn(b);
    return *(uint32_t*)&p;
}

// ---------------- prepass: W fp32 -> fp16 ----------------
__global__ void __launch_bounds__(256, 1) conv_w_kernel(const float* __restrict__ w) {
    const size_t i = (size_t)blockIdx.x * 256 + threadIdx.x;   // float4 index
    float4 v = ((const float4*)w)[i];
    ((uint2*)g_wh)[i] = make_uint2(pack_h2(v.x, v.y), pack_h2(v.z, v.w));
}

// ---------------- main kernel ----------------
// CTA: 64(M) x 256(N) for one f. 8 warps; warp tile 16x128. 2 CTAs/SM.
__global__ void __launch_bounds__(256, 2) nlinear_mma_kernel(
    const float* __restrict__ x,
    const float* __restrict__ bias,
    float* __restrict__ out)
{
    __shared__ __align__(16) __half As[2][MT * SA];        // [stage][m][k]
    __shared__ __align__(16) __half Bs[2][KP * SB];        // [stage][k][n]
    __shared__ float sbias[DOUT];

    const int tid  = threadIdx.x;
    const int lane = tid & 31;
    const int wid  = tid >> 5;
    const int mtile = blockIdx.x;   // 0..63
    const int f     = blockIdx.y;   // 0..63

    const int warp_m = (wid & 3) * 16;    // 0,16,32,48
    const int warp_n = (wid >> 2) * 128;  // 0 or 128

    sbias[tid] = bias[f * DOUT + tid];

    float acc[16][4];
#pragma unroll
    for (int nt = 0; nt < 16; nt++)
#pragma unroll
        for (int q = 0; q < 4; q++) acc[nt][q] = 0.0f;

    const float* xb = x + (size_t)(mtile * MT) * (F_DIM * DIN) + (size_t)f * DIN;
    const __half* whb = g_wh + (size_t)f * (DIN * DOUT);

    // ldmatrix addresses
    const uint32_t As_base = smem_u32(As);
    const uint32_t Bs_base = smem_u32(Bs);
    const uint32_t a_addr0 = As_base +
        (uint32_t)(((warp_m + (lane & 15)) * SA + (lane >> 4) * 8) * 2);
    const uint32_t a_stage = MT * SA * 2;     // As stage offset (bytes)
    const uint32_t a_khalf = 16 * 2;          // +16 k cols (bytes)

    const uint32_t b_row  = (lane & 7) + ((lane >> 3) & 1) * 8;
    const uint32_t b_col8 = (lane & 16) >> 1;
    const uint32_t b_addr0 = Bs_base + (uint32_t)((b_row * SB + warp_n + b_col8) * 2);
    const uint32_t b_stage = KP * SB * 2;     // Bs stage offset (bytes)
    const uint32_t b_khalf = 16 * SB * 2;     // +16 k rows (bytes)

    // x load map: 64 rows x 32 k = 512 float4 -> 2 per thread
    const int xr = tid >> 3;            // row 0..31 (+32 on second it)
    const int xc = (tid & 7) * 4;       // float col 0..28
    // W cp.async map per stage: 1024 8-half chunks: idx = it*256+tid (it<4)

    float4 nx[2];

    // ---- prologue: panel 0 ----
    {
#pragma unroll
        for (int it = 0; it < 4; it++) {
            const int idx = it * 256 + tid;
            const int row = idx >> 5;          // 0..31
            const int c16 = idx & 31;
            const __half* src = whb + (size_t)row * DOUT + c16 * 8;
            const uint32_t dst = Bs_base + (uint32_t)(row * SB + c16 * 8) * 2;
            CP_ASYNC16(dst, src);
        }
        CP_COMMIT();
#pragma unroll
        for (int it = 0; it < 2; it++) {
            const int r = it * 32 + xr;
            nx[it] = *(const float4*)(xb + (size_t)r * (F_DIM * DIN) + xc);
        }
#pragma unroll
        for (int it = 0; it < 2; it++) {
            const int r = it * 32 + xr;
            *(uint2*)&As[0][r * SA + xc] =
                make_uint2(pack_h2(nx[it].x, nx[it].y), pack_h2(nx[it].z, nx[it].w));
        }
        CP_WAIT0();
        __syncthreads();
    }

#pragma unroll
    for (int p = 0; p < 8; p++) {
        const int stage = p & 1;
        const bool more = p < 7;
        const int nk = (p + 1) * KP;

        // ---- prefetch panel p+1 (W cp.async + x LDG) ----
        if (more) {
#pragma unroll
            for (int it = 0; it < 4; it++) {
                const int idx = it * 256 + tid;
                const int row = idx >> 5;
                const int c16 = idx & 31;
                const __half* src = whb + (size_t)(nk + row) * DOUT + c16 * 8;
                const uint32_t dst = Bs_base +
                    (uint32_t)((stage ^ 1) * (KP * SB) + row * SB + c16 * 8) * 2;
                CP_ASYNC16(dst, src);
            }
            CP_COMMIT();
#pragma unroll
            for (int it = 0; it < 2; it++) {
                const int r = it * 32 + xr;
                nx[it] = *(const float4*)(xb + (size_t)r * (F_DIM * DIN) + nk + xc);
            }
        }

        // ---- MMAs for panel p ----
        uint32_t Ah[2][4];
        const uint32_t abase = a_addr0 + stage * a_stage;
        LDSM4(Ah[0], abase);
        LDSM4(Ah[1], abase + a_khalf);
        const uint32_t bbase = b_addr0 + stage * b_stage;
#pragma unroll
        for (int nc = 0; nc < 8; nc++) {
            uint32_t B0[4], B1[4];
            const uint32_t ba = bbase + nc * 16 * 2;
            LDSM4T(B0, ba);
            LDSM4T(B1, ba + b_khalf);
#pragma unroll
            for (int nt = 0; nt < 2; nt++) {
                float* c = acc[nc * 2 + nt];
                MMA16816F16(c, Ah[0], B0[2*nt], B0[2*nt+1]);
                MMA16816F16(c, Ah[1], B1[2*nt], B1[2*nt+1]);
            }
        }

        if (more) {
            // convert next x into the ALTERNATE As buffer (no readers there)
#pragma unroll
            for (int it = 0; it < 2; it++) {
                const int r = it * 32 + xr;
                *(uint2*)&As[stage ^ 1][r * SA + xc] =
                    make_uint2(pack_h2(nx[it].x, nx[it].y),
                               pack_h2(nx[it].z, nx[it].w));
            }
            CP_WAIT0();
            __syncthreads();   // one barrier per panel
        }
    }

    // ---- epilogue ----
    const int r_lane = lane >> 2;
    const int c_lane = (lane & 3) * 2;
#pragma unroll
    for (int nt = 0; nt < 16; nt++) {
        const int col = warp_n + nt * 8 + c_lane;
        const int row0 = mtile * MT + warp_m + r_lane;
        float* o0 = out + (size_t)row0 * (F_DIM * DOUT) + (size_t)f * DOUT + col;
        *(float2*)o0 = make_float2(acc[nt][0] + sbias[col],
                                   acc[nt][1] + sbias[col + 1]);
        float* o1 = o0 + 8 * (F_DIM * DOUT);
        *(float2*)o1 = make_float2(acc[nt][2] + sbias[col],
                                   acc[nt][3] + sbias[col + 1]);
    }
}

extern "C" void kernel_launch(void* const* d_in, const int* in_sizes, int n_in,
                              void* d_out, int out_size)
{
    const float* x = (n_in > 0) ? (const float*)d_in[0] : nullptr;
    const float* w = (n_in > 1) ? (const float*)d_in[1] : nullptr;
    const float* b = (n_in > 2) ? (const float*)d_in[2] : nullptr;
    for (int i = 0; i < n_in; i++) {
        if (in_sizes[i] == B_DIM * F_DIM * DIN)     x = (const float*)d_in[i];
        else if (in_sizes[i] == F_DIM * DIN * DOUT) w = (const float*)d_in[i];
        else if (in_sizes[i] == F_DIM * DOUT)       b = (const float*)d_in[i];
    }
    float* out = (float*)d_out;

    conv_w_kernel<<<4096, 256>>>(w);
    nlinear_mma_kernel<<<dim3(B_DIM / MT, F_DIM), 256>>>(x, b, out);
}

// round 13
// speedup vs baseline: 4.7209x; 1.0023x over previous
#include <cuda_runtime.h>
#include <cuda_fp16.h>
#include <cstdint>

// NLinear: out[b,f,o] = sum_i x[b,f,i] * W[f,i,o] + bias[f,o]
// B=4096, F=64, DIN=DOUT=256, fp32 in/out.
//
// Round-12: fp16 mma.sync, pre-converted W, cp.async W stages, KP=32,
// double-buffered As+Bs, one barrier per panel.
// NEW: warp tile 32x64 (2m x 4n warps) -> 12 ldmatrix/warp/panel instead of
// 18: cuts L1/shared LDSM traffic 33% (L1 was 68.6% busy = bottleneck).

#define B_DIM  4096
#define F_DIM  64
#define DIN    256
#define DOUT   256
#define KP     32          // K panel
#define MT     64          // CTA M tile
#define SA     40          // As row stride (fp16): 80B rows, ldmatrix conflict-free
#define SB     264         // Bs row stride (fp16): 528B rows, ldmatrix conflict-free

// pre-converted W, fp16, layout [f][i][o]
static __device__ __half g_wh[F_DIM * DIN * DOUT];

__device__ __forceinline__ uint32_t smem_u32(const void* p) {
    uint32_t a;
    asm("{ .reg .u64 t; cvta.to.shared.u64 t, %1; cvt.u32.u64 %0, t; }"
        : "=r"(a) : "l"(p));
    return a;
}

#define LDSM4(R, addr) \
    asm volatile("ldmatrix.sync.aligned.m8n8.x4.shared.b16 {%0,%1,%2,%3}, [%4];" \
                 : "=r"((R)[0]), "=r"((R)[1]), "=r"((R)[2]), "=r"((R)[3]) \
                 : "r"(addr))

#define LDSM4T(R, addr) \
    asm volatile("ldmatrix.sync.aligned.m8n8.x4.trans.shared.b16 {%0,%1,%2,%3}, [%4];" \
                 : "=r"((R)[0]), "=r"((R)[1]), "=r"((R)[2]), "=r"((R)[3]) \
                 : "r"(addr))

#define MMA16816F16(C, A, b0, b1) \
    asm volatile("mma.sync.aligned.m16n8k16.row.col.f32.f16.f16.f32 " \
                 "{%0,%1,%2,%3}, {%4,%5,%6,%7}, {%8,%9}, {%0,%1,%2,%3};" \
                 : "+f"((C)[0]), "+f"((C)[1]), "+f"((C)[2]), "+f"((C)[3]) \
                 : "r"((A)[0]), "r"((A)[1]), "r"((A)[2]), "r"((A)[3]), \
                   "r"(b0), "r"(b1))

#define CP_ASYNC16(dst, src) \
    asm volatile("cp.async.cg.shared.global [%0], [%1], 16;" :: "r"(dst), "l"(src))
#define CP_COMMIT() asm volatile("cp.async.commit_group;" ::: "memory")
#define CP_WAIT0()  asm volatile("cp.async.wait_group 0;" ::: "memory")

__device__ __forceinline__ uint32_t pack_h2(float a, float b) {
    __half2 p;
    p.x = __float2half_rn(a);
    p.y = __float2half_rn(b);
    return *(uint32_t*)&p;
}

// ---------------- prepass: W fp32 -> fp16 ----------------
__global__ void __launch_bounds__(256, 1) conv_w_kernel(const float* __restrict__ w) {
    const size_t i = (size_t)blockIdx.x * 256 + threadIdx.x;   // float4 index
    float4 v = ((const float4*)w)[i];
    ((uint2*)g_wh)[i] = make_uint2(pack_h2(v.x, v.y), pack_h2(v.z, v.w));
}

// ---------------- main kernel ----------------
// CTA: 64(M) x 256(N) for one f. 8 warps; warp tile 32x64 (2m x 4n). 2 CTAs/SM.
__global__ void __launch_bounds__(256, 2) nlinear_mma_kernel(
    const float* __restrict__ x,
    const float* __restrict__ bias,
    float* __restrict__ out)
{
    __shared__ __align__(16) __half As[2][MT * SA];        // [stage][m][k]
    __shared__ __align__(16) __half Bs[2][KP * SB];        // [stage][k][n]
    __shared__ float sbias[DOUT];

    const int tid  = threadIdx.x;
    const int lane = tid & 31;
    const int wid  = tid >> 5;
    const int mtile = blockIdx.x;   // 0..63
    const int f     = blockIdx.y;   // 0..63

    const int warp_m = (wid & 1) * 32;    // 0 or 32
    const int warp_n = (wid >> 1) * 64;   // 0,64,128,192

    sbias[tid] = bias[f * DOUT + tid];

    float acc[2][8][4];   // [mt][n-tile][quad]
#pragma unroll
    for (int mt = 0; mt < 2; mt++)
#pragma unroll
        for (int nt = 0; nt < 8; nt++)
#pragma unroll
            for (int q = 0; q < 4; q++) acc[mt][nt][q] = 0.0f;

    const float* xb = x + (size_t)(mtile * MT) * (F_DIM * DIN) + (size_t)f * DIN;
    const __half* whb = g_wh + (size_t)f * (DIN * DOUT);

    // ldmatrix addresses
    const uint32_t As_base = smem_u32(As);
    const uint32_t Bs_base = smem_u32(Bs);
    const uint32_t a_addr0 = As_base +
        (uint32_t)(((warp_m + (lane & 15)) * SA + (lane >> 4) * 8) * 2);
    const uint32_t a_stage = MT * SA * 2;     // As stage offset (bytes)
    const uint32_t a_khalf = 16 * 2;          // +16 k cols (bytes)
    const uint32_t a_mtile = 16 * SA * 2;     // +16 m rows (bytes)

    const uint32_t b_row  = (lane & 7) + ((lane >> 3) & 1) * 8;
    const uint32_t b_col8 = (lane & 16) >> 1;
    const uint32_t b_addr0 = Bs_base + (uint32_t)((b_row * SB + warp_n + b_col8) * 2);
    const uint32_t b_stage = KP * SB * 2;     // Bs stage offset (bytes)
    const uint32_t b_khalf = 16 * SB * 2;     // +16 k rows (bytes)

    // x load map: 64 rows x 32 k = 512 float4 -> 2 per thread
    const int xr = tid >> 3;            // row 0..31 (+32 on second it)
    const int xc = (tid & 7) * 4;       // float col 0..28

    float4 nx[2];

    // ---- prologue: panel 0 ----
    {
#pragma unroll
        for (int it = 0; it < 4; it++) {
            const int idx = it * 256 + tid;
            const int row = idx >> 5;          // 0..31
            const int c16 = idx & 31;
            const __half* src = whb + (size_t)row * DOUT + c16 * 8;
            const uint32_t dst = Bs_base + (uint32_t)(row * SB + c16 * 8) * 2;
            CP_ASYNC16(dst, src);
        }
        CP_COMMIT();
#pragma unroll
        for (int it = 0; it < 2; it++) {
            const int r = it * 32 + xr;
            nx[it] = *(const float4*)(xb + (size_t)r * (F_DIM * DIN) + xc);
        }
#pragma unroll
        for (int it = 0; it < 2; it++) {
            const int r = it * 32 + xr;
            *(uint2*)&As[0][r * SA + xc] =
                make_uint2(pack_h2(nx[it].x, nx[it].y), pack_h2(nx[it].z, nx[it].w));
        }
        CP_WAIT0();
        __syncthreads();
    }

#pragma unroll
    for (int p = 0; p < 8; p++) {
        const int stage = p & 1;
        const bool more = p < 7;
        const int nk = (p + 1) * KP;

        // ---- prefetch panel p+1 (W cp.async + x LDG) ----
        if (more) {
#pragma unroll
            for (int it = 0; it < 4; it++) {
                const int idx = it * 256 + tid;
                const int row = idx >> 5;
                const int c16 = idx & 31;
                const __half* src = whb + (size_t)(nk + row) * DOUT + c16 * 8;
                const uint32_t dst = Bs_base +
                    (uint32_t)((stage ^ 1) * (KP * SB) + row * SB + c16 * 8) * 2;
                CP_ASYNC16(dst, src);
            }
            CP_COMMIT();
#pragma unroll
            for (int it = 0; it < 2; it++) {
                const int r = it * 32 + xr;
                nx[it] = *(const float4*)(xb + (size_t)r * (F_DIM * DIN) + nk + xc);
            }
        }

        // ---- MMAs for panel p ----
        uint32_t Ah[2][2][4];   // [mt][khalf]
        const uint32_t abase = a_addr0 + stage * a_stage;
#pragma unroll
        for (int mt = 0; mt < 2; mt++) {
            LDSM4(Ah[mt][0], abase + mt * a_mtile);
            LDSM4(Ah[mt][1], abase + mt * a_mtile + a_khalf);
        }
        const uint32_t bbase = b_addr0 + stage * b_stage;
#pragma unroll
        for (int nc = 0; nc < 4; nc++) {
            uint32_t B0[4], B1[4];
            const uint32_t ba = bbase + nc * 16 * 2;
            LDSM4T(B0, ba);
            LDSM4T(B1, ba + b_khalf);
#pragma unroll
            for (int mt = 0; mt < 2; mt++) {
#pragma unroll
                for (int nt = 0; nt < 2; nt++) {
                    float* c = acc[mt][nc * 2 + nt];
                    MMA16816F16(c, Ah[mt][0], B0[2*nt], B0[2*nt+1]);
                    MMA16816F16(c, Ah[mt][1], B1[2*nt], B1[2*nt+1]);
                }
            }
        }

        if (more) {
            // convert next x into the ALTERNATE As buffer
#pragma unroll
            for (int it = 0; it < 2; it++) {
                const int r = it * 32 + xr;
                *(uint2*)&As[stage ^ 1][r * SA + xc] =
                    make_uint2(pack_h2(nx[it].x, nx[it].y),
                               pack_h2(nx[it].z, nx[it].w));
            }
            CP_WAIT0();
            __syncthreads();   // one barrier per panel
        }
    }

    // ---- epilogue ----
    const int r_lane = lane >> 2;
    const int c_lane = (lane & 3) * 2;
#pragma unroll
    for (int mt = 0; mt < 2; mt++) {
#pragma unroll
        for (int nt = 0; nt < 8; nt++) {
            const int col = warp_n + nt * 8 + c_lane;
            const int row0 = mtile * MT + warp_m + mt * 16 + r_lane;
            float* o0 = out + (size_t)row0 * (F_DIM * DOUT) + (size_t)f * DOUT + col;
            *(float2*)o0 = make_float2(acc[mt][nt][0] + sbias[col],
                                       acc[mt][nt][1] + sbias[col + 1]);
            float* o1 = o0 + 8 * (F_DIM * DOUT);
            *(float2*)o1 = make_float2(acc[mt][nt][2] + sbias[col],
                                       acc[mt][nt][3] + sbias[col + 1]);
        }
    }
}

extern "C" void kernel_launch(void* const* d_in, const int* in_sizes, int n_in,
                              void* d_out, int out_size)
{
    const float* x = (n_in > 0) ? (const float*)d_in[0] : nullptr;
    const float* w = (n_in > 1) ? (const float*)d_in[1] : nullptr;
    const float* b = (n_in > 2) ? (const float*)d_in[2] : nullptr;
    for (int i = 0; i < n_in; i++) {
        if (in_sizes[i] == B_DIM * F_DIM * DIN)     x = (const float*)d_in[i];
        else if (in_sizes[i] == F_DIM * DIN * DOUT) w = (const float*)d_in[i];
        else if (in_sizes[i] == F_DIM * DOUT)       b = (const float*)d_in[i];
    }
    float* out = (float*)d_out;

    conv_w_kernel<<<4096, 256>>>(w);
    nlinear_mma_kernel<<<dim3(B_DIM / MT, F_DIM), 256>>>(x, b, out);
}

// round 14
// speedup vs baseline: 4.7277x; 1.0014x over previous
#include <cuda_runtime.h>
#include <cuda_fp16.h>
#include <cstdint>

// NLinear: out[b,f,o] = sum_i x[b,f,i] * W[f,i,o] + bias[f,o]
// B=4096, F=64, DIN=DOUT=256, fp32 in/out.
//
// Round-13: fp16 mma.sync, pre-converted W, cp.async W (distance-1),
// KP=32, double-buffered As+Bs, one barrier per panel, warp tile 32x64.
// NEW: x prefetch DISTANCE 2 (register ping-pong) — the convert was
// stalling ~600cyc/panel on a distance-1 DRAM load.

#define B_DIM  4096
#define F_DIM  64
#define DIN    256
#define DOUT   256
#define KP     32          // K panel
#define MT     64          // CTA M tile
#define SA     40          // As row stride (fp16): 80B rows, ldmatrix conflict-free
#define SB     264         // Bs row stride (fp16): 528B rows, ldmatrix conflict-free

// pre-converted W, fp16, layout [f][i][o]
static __device__ __half g_wh[F_DIM * DIN * DOUT];

__device__ __forceinline__ uint32_t smem_u32(const void* p) {
    uint32_t a;
    asm("{ .reg .u64 t; cvta.to.shared.u64 t, %1; cvt.u32.u64 %0, t; }"
        : "=r"(a) : "l"(p));
    return a;
}

#define LDSM4(R, addr) \
    asm volatile("ldmatrix.sync.aligned.m8n8.x4.shared.b16 {%0,%1,%2,%3}, [%4];" \
                 : "=r"((R)[0]), "=r"((R)[1]), "=r"((R)[2]), "=r"((R)[3]) \
                 : "r"(addr))

#define LDSM4T(R, addr) \
    asm volatile("ldmatrix.sync.aligned.m8n8.x4.trans.shared.b16 {%0,%1,%2,%3}, [%4];" \
                 : "=r"((R)[0]), "=r"((R)[1]), "=r"((R)[2]), "=r"((R)[3]) \
                 : "r"(addr))

#define MMA16816F16(C, A, b0, b1) \
    asm volatile("mma.sync.aligned.m16n8k16.row.col.f32.f16.f16.f32 " \
                 "{%0,%1,%2,%3}, {%4,%5,%6,%7}, {%8,%9}, {%0,%1,%2,%3};" \
                 : "+f"((C)[0]), "+f"((C)[1]), "+f"((C)[2]), "+f"((C)[3]) \
                 : "r"((A)[0]), "r"((A)[1]), "r"((A)[2]), "r"((A)[3]), \
                   "r"(b0), "r"(b1))

#define CP_ASYNC16(dst, src) \
    asm volatile("cp.async.cg.shared.global [%0], [%1], 16;" :: "r"(dst), "l"(src))
#define CP_COMMIT() asm volatile("cp.async.commit_group;" ::: "memory")
#define CP_WAIT0()  asm volatile("cp.async.wait_group 0;" ::: "memory")

__device__ __forceinline__ uint32_t pack_h2(float a, float b) {
    __half2 p;
    p.x = __float2half_rn(a);
    p.y = __float2half_rn(b);
    return *(uint32_t*)&p;
}

// ---------------- prepass: W fp32 -> fp16 ----------------
__global__ void __launch_bounds__(256, 1) conv_w_kernel(const float* __restrict__ w) {
    const size_t i = (size_t)blockIdx.x * 256 + threadIdx.x;   // float4 index
    float4 v = ((const float4*)w)[i];
    ((uint2*)g_wh)[i] = make_uint2(pack_h2(v.x, v.y), pack_h2(v.z, v.w));
}

// ---------------- main kernel ----------------
// CTA: 64(M) x 256(N) for one f. 8 warps; warp tile 32x64 (2m x 4n). 2 CTAs/SM.
__global__ void __launch_bounds__(256, 2) nlinear_mma_kernel(
    const float* __restrict__ x,
    const float* __restrict__ bias,
    float* __restrict__ out)
{
    __shared__ __align__(16) __half As[2][MT * SA];        // [stage][m][k]
    __shared__ __align__(16) __half Bs[2][KP * SB];        // [stage][k][n]
    __shared__ float sbias[DOUT];

    const int tid  = threadIdx.x;
    const int lane = tid & 31;
    const int wid  = tid >> 5;
    const int mtile = blockIdx.x;   // 0..63
    const int f     = blockIdx.y;   // 0..63

    const int warp_m = (wid & 1) * 32;    // 0 or 32
    const int warp_n = (wid >> 1) * 64;   // 0,64,128,192

    sbias[tid] = bias[f * DOUT + tid];

    float acc[2][8][4];   // [mt][n-tile][quad]
#pragma unroll
    for (int mt = 0; mt < 2; mt++)
#pragma unroll
        for (int nt = 0; nt < 8; nt++)
#pragma unroll
            for (int q = 0; q < 4; q++) acc[mt][nt][q] = 0.0f;

    const float* xb = x + (size_t)(mtile * MT) * (F_DIM * DIN) + (size_t)f * DIN;
    const __half* whb = g_wh + (size_t)f * (DIN * DOUT);

    // ldmatrix addresses
    const uint32_t As_base = smem_u32(As);
    const uint32_t Bs_base = smem_u32(Bs);
    const uint32_t a_addr0 = As_base +
        (uint32_t)(((warp_m + (lane & 15)) * SA + (lane >> 4) * 8) * 2);
    const uint32_t a_stage = MT * SA * 2;     // As stage offset (bytes)
    const uint32_t a_khalf = 16 * 2;          // +16 k cols (bytes)
    const uint32_t a_mtile = 16 * SA * 2;     // +16 m rows (bytes)

    const uint32_t b_row  = (lane & 7) + ((lane >> 3) & 1) * 8;
    const uint32_t b_col8 = (lane & 16) >> 1;
    const uint32_t b_addr0 = Bs_base + (uint32_t)((b_row * SB + warp_n + b_col8) * 2);
    const uint32_t b_stage = KP * SB * 2;     // Bs stage offset (bytes)
    const uint32_t b_khalf = 16 * SB * 2;     // +16 k rows (bytes)

    // x load map: 64 rows x 32 k = 512 float4 -> 2 per thread
    const int xr = tid >> 3;            // row 0..31 (+32 on second it)
    const int xc = (tid & 7) * 4;       // float col 0..28

    float4 nx1[2];   // x data for the NEXT panel (to convert this panel)
    float4 nx2[2];   // x data for panel after next (in flight)

    // ---- prologue ----
    {
        // W(0) cp.async
#pragma unroll
        for (int it = 0; it < 4; it++) {
            const int idx = it * 256 + tid;
            const int row = idx >> 5;          // 0..31
            const int c16 = idx & 31;
            const __half* src = whb + (size_t)row * DOUT + c16 * 8;
            const uint32_t dst = Bs_base + (uint32_t)(row * SB + c16 * 8) * 2;
            CP_ASYNC16(dst, src);
        }
        CP_COMMIT();
        // x(0) -> convert -> As[0]
#pragma unroll
        for (int it = 0; it < 2; it++) {
            const int r = it * 32 + xr;
            float4 v = *(const float4*)(xb + (size_t)r * (F_DIM * DIN) + xc);
            *(uint2*)&As[0][r * SA + xc] =
                make_uint2(pack_h2(v.x, v.y), pack_h2(v.z, v.w));
        }
        // x(1) in flight
#pragma unroll
        for (int it = 0; it < 2; it++) {
            const int r = it * 32 + xr;
            nx1[it] = *(const float4*)(xb + (size_t)r * (F_DIM * DIN) + KP + xc);
        }
        CP_WAIT0();
        __syncthreads();
    }

#pragma unroll
    for (int p = 0; p < 8; p++) {
        const int stage = p & 1;
        const bool more  = p < 7;    // panel p+1 exists
        const bool more2 = p < 6;    // panel p+2 exists

        // ---- W(p+1) cp.async ----
        if (more) {
            const int nk = (p + 1) * KP;
#pragma unroll
            for (int it = 0; it < 4; it++) {
                const int idx = it * 256 + tid;
                const int row = idx >> 5;
                const int c16 = idx & 31;
                const __half* src = whb + (size_t)(nk + row) * DOUT + c16 * 8;
                const uint32_t dst = Bs_base +
                    (uint32_t)((stage ^ 1) * (KP * SB) + row * SB + c16 * 8) * 2;
                CP_ASYNC16(dst, src);
            }
            CP_COMMIT();
        }
        // ---- x(p+2) LDG (distance 2) ----
        if (more2) {
            const int nk2 = (p + 2) * KP;
#pragma unroll
            for (int it = 0; it < 2; it++) {
                const int r = it * 32 + xr;
                nx2[it] = *(const float4*)(xb + (size_t)r * (F_DIM * DIN) + nk2 + xc);
            }
        }

        // ---- MMAs for panel p ----
        uint32_t Ah[2][2][4];   // [mt][khalf]
        const uint32_t abase = a_addr0 + stage * a_stage;
#pragma unroll
        for (int mt = 0; mt < 2; mt++) {
            LDSM4(Ah[mt][0], abase + mt * a_mtile);
            LDSM4(Ah[mt][1], abase + mt * a_mtile + a_khalf);
        }
        const uint32_t bbase = b_addr0 + stage * b_stage;
#pragma unroll
        for (int nc = 0; nc < 4; nc++) {
            uint32_t B0[4], B1[4];
            const uint32_t ba = bbase + nc * 16 * 2;
            LDSM4T(B0, ba);
            LDSM4T(B1, ba + b_khalf);
#pragma unroll
            for (int mt = 0; mt < 2; mt++) {
#pragma unroll
                for (int nt = 0; nt < 2; nt++) {
                    float* c = acc[mt][nc * 2 + nt];
                    MMA16816F16(c, Ah[mt][0], B0[2*nt], B0[2*nt+1]);
                    MMA16816F16(c, Ah[mt][1], B1[2*nt], B1[2*nt+1]);
                }
            }
        }

        if (more) {
            // convert x(p+1) (arrived a full panel ago) into alternate As
#pragma unroll
            for (int it = 0; it < 2; it++) {
                const int r = it * 32 + xr;
                *(uint2*)&As[stage ^ 1][r * SA + xc] =
                    make_uint2(pack_h2(nx1[it].x, nx1[it].y),
                               pack_h2(nx1[it].z, nx1[it].w));
            }
            CP_WAIT0();
            __syncthreads();   // one barrier per panel
            // rotate prefetch registers (renamed by unroll)
#pragma unroll
            for (int it = 0; it < 2; it++) nx1[it] = nx2[it];
        }
    }

    // ---- epilogue ----
    const int r_lane = lane >> 2;
    const int c_lane = (lane & 3) * 2;
#pragma unroll
    for (int mt = 0; mt < 2; mt++) {
#pragma unroll
        for (int nt = 0; nt < 8; nt++) {
            const int col = warp_n + nt * 8 + c_lane;
            const int row0 = mtile * MT + warp_m + mt * 16 + r_lane;
            float* o0 = out + (size_t)row0 * (F_DIM * DOUT) + (size_t)f * DOUT + col;
            *(float2*)o0 = make_float2(acc[mt][nt][0] + sbias[col],
                                       acc[mt][nt][1] + sbias[col + 1]);
            float* o1 = o0 + 8 * (F_DIM * DOUT);
            *(float2*)o1 = make_float2(acc[mt][nt][2] + sbias[col],
                                       acc[mt][nt][3] + sbias[col + 1]);
        }
    }
}

extern "C" void kernel_launch(void* const* d_in, const int* in_sizes, int n_in,
                              void* d_out, int out_size)
{
    const float* x = (n_in > 0) ? (const float*)d_in[0] : nullptr;
    const float* w = (n_in > 1) ? (const float*)d_in[1] : nullptr;
    const float* b = (n_in > 2) ? (const float*)d_in[2] : nullptr;
    for (int i = 0; i < n_in; i++) {
        if (in_sizes[i] == B_DIM * F_DIM * DIN)     x = (const float*)d_in[i];
        else if (in_sizes[i] == F_DIM * DIN * DOUT) w = (const float*)d_in[i];
        else if (in_sizes[i] == F_DIM * DOUT)       b = (const float*)d_in[i];
    }
    float* out = (float*)d_out;

    conv_w_kernel<<<4096, 256>>>(w);
    nlinear_mma_kernel<<<dim3(B_DIM / MT, F_DIM), 256>>>(x, b, out);
}

// round 16
// speedup vs baseline: 5.2663x; 1.1139x over previous
#include <cuda_runtime.h>
#include <cuda_fp16.h>
#include <cstdint>

// NLinear: out[b,f,o] = sum_i x[b,f,i] * W[f,i,o] + bias[f,o]
// B=4096, F=64, DIN=DOUT=256, fp32 in/out.
//
// Round-14: RESIDENT-W design. One 512-thread CTA holds the ENTIRE padded
// W[f] (fp16, 135 KB) in dynamic smem, loaded once by cp.async in the
// prologue. The 8-panel main loop has NO per-panel W staging, no cp.async
// waits — only the small x-convert double buffer + one barrier per panel.

#define B_DIM  4096
#define F_DIM  64
#define DIN    256
#define DOUT   256
#define KP     32          // K panel
#define MT     128         // CTA M tile
#define NTHR   512         // 16 warps
#define SA     40          // As row stride (fp16): 80B rows, ldmatrix conflict-free
#define SB     264         // Ws row stride (fp16): 528B rows, ldmatrix conflict-free

// smem layout (bytes)
#define WS_BYTES   (DIN * SB * 2)            // 256 rows x 264 halves = 135168
#define AS_STAGE   (MT * SA * 2)             // 10240
#define AS_OFF     WS_BYTES
#define BIAS_OFF   (AS_OFF + 2 * AS_STAGE)   // 155648
#define SMEM_TOTAL (BIAS_OFF + DOUT * 4)     // 156672

// pre-converted W, fp16, layout [f][i][o]
static __device__ __half g_wh[F_DIM * DIN * DOUT];

__device__ __forceinline__ uint32_t smem_u32(const void* p) {
    uint32_t a;
    asm("{ .reg .u64 t; cvta.to.shared.u64 t, %1; cvt.u32.u64 %0, t; }"
        : "=r"(a) : "l"(p));
    return a;
}

#define LDSM4(R, addr) \
    asm volatile("ldmatrix.sync.aligned.m8n8.x4.shared.b16 {%0,%1,%2,%3}, [%4];" \
                 : "=r"((R)[0]), "=r"((R)[1]), "=r"((R)[2]), "=r"((R)[3]) \
                 : "r"(addr))

#define LDSM4T(R, addr) \
    asm volatile("ldmatrix.sync.aligned.m8n8.x4.trans.shared.b16 {%0,%1,%2,%3}, [%4];" \
                 : "=r"((R)[0]), "=r"((R)[1]), "=r"((R)[2]), "=r"((R)[3]) \
                 : "r"(addr))

#define MMA16816F16(C, A, b0, b1) \
    asm volatile("mma.sync.aligned.m16n8k16.row.col.f32.f16.f16.f32 " \
                 "{%0,%1,%2,%3}, {%4,%5,%6,%7}, {%8,%9}, {%0,%1,%2,%3};" \
                 : "+f"((C)[0]), "+f"((C)[1]), "+f"((C)[2]), "+f"((C)[3]) \
                 : "r"((A)[0]), "r"((A)[1]), "r"((A)[2]), "r"((A)[3]), \
                   "r"(b0), "r"(b1))

#define CP_ASYNC16(dst, src) \
    asm volatile("cp.async.cg.shared.global [%0], [%1], 16;" :: "r"(dst), "l"(src))
#define CP_COMMIT() asm volatile("cp.async.commit_group;" ::: "memory")
#define CP_WAIT0()  asm volatile("cp.async.wait_group 0;" ::: "memory")

__device__ __forceinline__ uint32_t pack_h2(float a, float b) {
    __half2 p;
    p.x = __float2half_rn(a);
    p.y = __float2half_rn(b);
    return *(uint32_t*)&p;
}

// ---------------- prepass: W fp32 -> fp16 ----------------
__global__ void __launch_bounds__(256, 1) conv_w_kernel(const float* __restrict__ w) {
    const size_t i = (size_t)blockIdx.x * 256 + threadIdx.x;   // float4 index
    float4 v = ((const float4*)w)[i];
    ((uint2*)g_wh)[i] = make_uint2(pack_h2(v.x, v.y), pack_h2(v.z, v.w));
}

// ---------------- main kernel ----------------
// CTA: 128(M) x 256(N) for one f. 16 warps (4m x 4n); warp tile 32x64.
__global__ void __launch_bounds__(NTHR, 1) nlinear_mma_kernel(
    const float* __restrict__ x,
    const float* __restrict__ bias,
    float* __restrict__ out)
{
    extern __shared__ __align__(16) char smem[];
    __half* Ws = (__half*)smem;                       // [k=256][n], stride SB
    __half* As = (__half*)(smem + AS_OFF);            // [2][m=128][k=32], stride SA
    float*  sbias = (float*)(smem + BIAS_OFF);

    const int tid  = threadIdx.x;
    const int lane = tid & 31;
    const int wid  = tid >> 5;
    const int mtile = blockIdx.x;   // 0..31
    const int f     = blockIdx.y;   // 0..63

    const int warp_m = (wid & 3) * 32;    // 0,32,64,96
    const int warp_n = (wid >> 2) * 64;   // 0,64,128,192

    if (tid < DOUT) sbias[tid] = bias[f * DOUT + tid];

    float acc[2][8][4];   // [mt][n-tile][quad]
#pragma unroll
    for (int mt = 0; mt < 2; mt++)
#pragma unroll
        for (int nt = 0; nt < 8; nt++)
#pragma unroll
            for (int q = 0; q < 4; q++) acc[mt][nt][q] = 0.0f;

    const float* xb = x + (size_t)(mtile * MT) * (F_DIM * DIN) + (size_t)f * DIN;
    const __half* whb = g_wh + (size_t)f * (DIN * DOUT);

    const uint32_t Ws_base = smem_u32(Ws);
    const uint32_t As_base = smem_u32(As);

    // A ldmatrix address (within a stage)
    const uint32_t a_addr0 = As_base +
        (uint32_t)(((warp_m + (lane & 15)) * SA + (lane >> 4) * 8) * 2);
    const uint32_t a_khalf = 16 * 2;          // +16 k cols
    const uint32_t a_mtile = 16 * SA * 2;     // +16 m rows

    // B ldmatrix address (k row within full Ws)
    const uint32_t b_row  = (lane & 7) + ((lane >> 3) & 1) * 8;
    const uint32_t b_col8 = (lane & 16) >> 1;
    const uint32_t b_addr0 = Ws_base + (uint32_t)((b_row * SB + warp_n + b_col8) * 2);
    const uint32_t b_kpanel = KP * SB * 2;    // +32 k rows
    const uint32_t b_khalf  = 16 * SB * 2;    // +16 k rows

    // x load map: 128 rows x 8 float4/row = 1024 float4 -> 2 per thread
    // idx = it*512 + tid: r = idx>>3 (0..127), c = (idx&7)*4
    float4 nx1[2], nx2[2];

    // ---- prologue ----
    {
        // whole W[f]: 256 rows x 32 16B-chunks = 8192 chunks -> 16 per thread
#pragma unroll
        for (int it = 0; it < 16; it++) {
            const int idx = it * NTHR + tid;
            const int row = idx >> 5;          // 0..255
            const int c16 = idx & 31;
            const __half* src = whb + (size_t)row * DOUT + c16 * 8;
            const uint32_t dst = Ws_base + (uint32_t)(row * SB + c16 * 8) * 2;
            CP_ASYNC16(dst, src);
        }
        CP_COMMIT();
        // x(0) -> convert -> As[0]
#pragma unroll
        for (int it = 0; it < 2; it++) {
            const int idx = it * NTHR + tid;
            const int r = idx >> 3;
            const int c = (idx & 7) * 4;
            float4 v = *(const float4*)(xb + (size_t)r * (F_DIM * DIN) + c);
            *(uint2*)&As[r * SA + c] =
                make_uint2(pack_h2(v.x, v.y), pack_h2(v.z, v.w));
        }
        // x(1) in flight
#pragma unroll
        for (int it = 0; it < 2; it++) {
            const int idx = it * NTHR + tid;
            const int r = idx >> 3;
            const int c = (idx & 7) * 4;
            nx1[it] = *(const float4*)(xb + (size_t)r * (F_DIM * DIN) + KP + c);
        }
        CP_WAIT0();
        __syncthreads();
    }

#pragma unroll
    for (int p = 0; p < 8; p++) {
        const int stage = p & 1;
        const bool more  = p < 7;
        const bool more2 = p < 6;

        // ---- x(p+2) LDG (distance 2) ----
        if (more2) {
            const int nk2 = (p + 2) * KP;
#pragma unroll
            for (int it = 0; it < 2; it++) {
                const int idx = it * NTHR + tid;
                const int r = idx >> 3;
                const int c = (idx & 7) * 4;
                nx2[it] = *(const float4*)(xb + (size_t)r * (F_DIM * DIN) + nk2 + c);
            }
        }

        // ---- MMAs for panel p (B direct from resident Ws) ----
        uint32_t Ah[2][2][4];   // [mt][khalf]
        const uint32_t abase = a_addr0 + stage * AS_STAGE;
#pragma unroll
        for (int mt = 0; mt < 2; mt++) {
            LDSM4(Ah[mt][0], abase + mt * a_mtile);
            LDSM4(Ah[mt][1], abase + mt * a_mtile + a_khalf);
        }
        const uint32_t bbase = b_addr0 + p * b_kpanel;
#pragma unroll
        for (int nc = 0; nc < 4; nc++) {
            uint32_t B0[4], B1[4];
            const uint32_t ba = bbase + nc * 16 * 2;
            LDSM4T(B0, ba);
            LDSM4T(B1, ba + b_khalf);
#pragma unroll
            for (int mt = 0; mt < 2; mt++) {
#pragma unroll
                for (int nt = 0; nt < 2; nt++) {
                    float* c = acc[mt][nc * 2 + nt];
                    MMA16816F16(c, Ah[mt][0], B0[2*nt], B0[2*nt+1]);
                    MMA16816F16(c, Ah[mt][1], B1[2*nt], B1[2*nt+1]);
                }
            }
        }

        if (more) {
            // convert x(p+1) into alternate As stage
#pragma unroll
            for (int it = 0; it < 2; it++) {
                const int idx = it * NTHR + tid;
                const int r = idx >> 3;
                const int c = (idx & 7) * 4;
                *(uint2*)&As[(stage ^ 1) * (AS_STAGE / 2) + r * SA + c] =
                    make_uint2(pack_h2(nx1[it].x, nx1[it].y),
                               pack_h2(nx1[it].z, nx1[it].w));
            }
            __syncthreads();   // the only barrier per panel
#pragma unroll
            for (int it = 0; it < 2; it++) nx1[it] = nx2[it];
        }
    }

    // ---- epilogue ----
    const int r_lane = lane >> 2;
    const int c_lane = (lane & 3) * 2;
#pragma unroll
    for (int mt = 0; mt < 2; mt++) {
#pragma unroll
        for (int nt = 0; nt < 8; nt++) {
            const int col = warp_n + nt * 8 + c_lane;
            const int row0 = mtile * MT + warp_m + mt * 16 + r_lane;
            float* o0 = out + (size_t)row0 * (F_DIM * DOUT) + (size_t)f * DOUT + col;
            *(float2*)o0 = make_float2(acc[mt][nt][0] + sbias[col],
                                       acc[mt][nt][1] + sbias[col + 1]);
            float* o1 = o0 + 8 * (F_DIM * DOUT);
            *(float2*)o1 = make_float2(acc[mt][nt][2] + sbias[col],
                                       acc[mt][nt][3] + sbias[col + 1]);
        }
    }
}

extern "C" void kernel_launch(void* const* d_in, const int* in_sizes, int n_in,
                              void* d_out, int out_size)
{
    const float* x = (n_in > 0) ? (const float*)d_in[0] : nullptr;
    const float* w = (n_in > 1) ? (const float*)d_in[1] : nullptr;
    const float* b = (n_in > 2) ? (const float*)d_in[2] : nullptr;
    for (int i = 0; i < n_in; i++) {
        if (in_sizes[i] == B_DIM * F_DIM * DIN)     x = (const float*)d_in[i];
        else if (in_sizes[i] == F_DIM * DIN * DOUT) w = (const float*)d_in[i];
        else if (in_sizes[i] == F_DIM * DOUT)       b = (const float*)d_in[i];
    }
    float* out = (float*)d_out;

    conv_w_kernel<<<4096, 256>>>(w);

    cudaFuncSetAttribute(nlinear_mma_kernel,
                         cudaFuncAttributeMaxDynamicSharedMemorySize, SMEM_TOTAL);
    nlinear_mma_kernel<<<dim3(B_DIM / MT, F_DIM), NTHR, SMEM_TOTAL>>>(x, b, out);
}

// round 17
// speedup vs baseline: 5.3347x; 1.0130x over previous
#include <cuda_runtime.h>
#include <cuda_fp16.h>
#include <cstdint>

// NLinear: out[b,f,o] = sum_i x[b,f,i] * W[f,i,o] + bias[f,o]
// B=4096, F=64, DIN=DOUT=256, fp32 in/out.
//
// Round-16: resident-W (135KB smem, loaded once, split into two cp.async
// halves overlapped with panels 0-3) + PER-M-GROUP NAMED BARRIERS: warps
// regrouped so each 4-warp m-group owns its 32 As rows; bar.sync 1+g,128
// replaces the CTA-wide barrier -> 4 decoupled pipelines per CTA.

#define B_DIM  4096
#define F_DIM  64
#define DIN    256
#define DOUT   256
#define KP     32          // K panel
#define MT     128         // CTA M tile
#define NTHR   512         // 16 warps
#define SA     40          // As row stride (fp16): ldmatrix conflict-free
#define SB     264         // Ws row stride (fp16): ldmatrix conflict-free

// smem layout (bytes)
#define WS_BYTES   (DIN * SB * 2)            // 135168
#define AS_STAGE   (MT * SA * 2)             // 10240
#define AS_OFF     WS_BYTES
#define BIAS_OFF   (AS_OFF + 2 * AS_STAGE)
#define SMEM_TOTAL (BIAS_OFF + DOUT * 4)     // 156672

// pre-converted W, fp16, layout [f][i][o]
static __device__ __half g_wh[F_DIM * DIN * DOUT];

__device__ __forceinline__ uint32_t smem_u32(const void* p) {
    uint32_t a;
    asm("{ .reg .u64 t; cvta.to.shared.u64 t, %1; cvt.u32.u64 %0, t; }"
        : "=r"(a) : "l"(p));
    return a;
}

#define LDSM4(R, addr) \
    asm volatile("ldmatrix.sync.aligned.m8n8.x4.shared.b16 {%0,%1,%2,%3}, [%4];" \
                 : "=r"((R)[0]), "=r"((R)[1]), "=r"((R)[2]), "=r"((R)[3]) \
                 : "r"(addr))

#define LDSM4T(R, addr) \
    asm volatile("ldmatrix.sync.aligned.m8n8.x4.trans.shared.b16 {%0,%1,%2,%3}, [%4];" \
                 : "=r"((R)[0]), "=r"((R)[1]), "=r"((R)[2]), "=r"((R)[3]) \
                 : "r"(addr))

#define MMA16816F16(C, A, b0, b1) \
    asm volatile("mma.sync.aligned.m16n8k16.row.col.f32.f16.f16.f32 " \
                 "{%0,%1,%2,%3}, {%4,%5,%6,%7}, {%8,%9}, {%0,%1,%2,%3};" \
                 : "+f"((C)[0]), "+f"((C)[1]), "+f"((C)[2]), "+f"((C)[3]) \
                 : "r"((A)[0]), "r"((A)[1]), "r"((A)[2]), "r"((A)[3]), \
                   "r"(b0), "r"(b1))

#define CP_ASYNC16(dst, src) \
    asm volatile("cp.async.cg.shared.global [%0], [%1], 16;" :: "r"(dst), "l"(src))
#define CP_COMMIT() asm volatile("cp.async.commit_group;" ::: "memory")
#define CP_WAIT0()  asm volatile("cp.async.wait_group 0;" ::: "memory")
#define CP_WAIT1()  asm volatile("cp.async.wait_group 1;" ::: "memory")
#define BAR_GRP(id) asm volatile("bar.sync %0, 128;" :: "r"(id) : "memory")

__device__ __forceinline__ uint32_t pack_h2(float a, float b) {
    __half2 p;
    p.x = __float2half_rn(a);
    p.y = __float2half_rn(b);
    return *(uint32_t*)&p;
}

// ---------------- prepass: W fp32 -> fp16 ----------------
__global__ void __launch_bounds__(256, 1) conv_w_kernel(const float* __restrict__ w) {
    const size_t i = (size_t)blockIdx.x * 256 + threadIdx.x;   // float4 index
    float4 v = ((const float4*)w)[i];
    ((uint2*)g_wh)[i] = make_uint2(pack_h2(v.x, v.y), pack_h2(v.z, v.w));
}

// ---------------- main kernel ----------------
// CTA: 128(M) x 256(N) for one f. 16 warps; m-group g = wid>>2 owns rows
// [32g, 32g+32); warp tile 32x64 (warp_n = (wid&3)*64).
__global__ void __launch_bounds__(NTHR, 1) nlinear_mma_kernel(
    const float* __restrict__ x,
    const float* __restrict__ bias,
    float* __restrict__ out)
{
    extern __shared__ __align__(16) char smem[];
    __half* Ws = (__half*)smem;                       // [k=256][n], stride SB
    __half* As = (__half*)(smem + AS_OFF);            // [2][m=128][k=32], stride SA
    float*  sbias = (float*)(smem + BIAS_OFF);

    const int tid  = threadIdx.x;
    const int lane = tid & 31;
    const int wid  = tid >> 5;
    const int grp  = wid >> 2;            // m-group 0..3
    const int gtid = tid & 127;           // thread within group
    const int bar_id = 1 + grp;
    const int mtile = blockIdx.x;         // 0..31
    const int f     = blockIdx.y;         // 0..63

    const int warp_m = grp * 32;          // 0,32,64,96
    const int warp_n = (wid & 3) * 64;    // 0,64,128,192

    if (tid < DOUT) sbias[tid] = bias[f * DOUT + tid];

    float acc[2][8][4];   // [mt][n-tile][quad]
#pragma unroll
    for (int mt = 0; mt < 2; mt++)
#pragma unroll
        for (int nt = 0; nt < 8; nt++)
#pragma unroll
            for (int q = 0; q < 4; q++) acc[mt][nt][q] = 0.0f;

    const float* xb = x + (size_t)(mtile * MT) * (F_DIM * DIN) + (size_t)f * DIN;
    const __half* whb = g_wh + (size_t)f * (DIN * DOUT);

    const uint32_t Ws_base = smem_u32(Ws);
    const uint32_t As_base = smem_u32(As);

    // A ldmatrix address (within a stage)
    const uint32_t a_addr0 = As_base +
        (uint32_t)(((warp_m + (lane & 15)) * SA + (lane >> 4) * 8) * 2);
    const uint32_t a_khalf = 16 * 2;
    const uint32_t a_mtile = 16 * SA * 2;

    // B ldmatrix address
    const uint32_t b_row  = (lane & 7) + ((lane >> 3) & 1) * 8;
    const uint32_t b_col8 = (lane & 16) >> 1;
    const uint32_t b_addr0 = Ws_base + (uint32_t)((b_row * SB + warp_n + b_col8) * 2);
    const uint32_t b_kpanel = KP * SB * 2;
    const uint32_t b_khalf  = 16 * SB * 2;

    // x map (per group): rows [warp_m, warp_m+32), 256 float4 -> 2/thread
    //   idx = it*128 + gtid: r = warp_m + (idx>>3), c = (idx&7)*4
    float4 nx1[2], nx2[2];

    // ---- prologue ----
    {
        // W k-rows 0..127 (group A)
#pragma unroll
        for (int it = 0; it < 8; it++) {
            const int idx = it * NTHR + tid;         // 0..4095
            const int row = idx >> 5;                // 0..127
            const int c16 = idx & 31;
            const __half* src = whb + (size_t)row * DOUT + c16 * 8;
            const uint32_t dst = Ws_base + (uint32_t)(row * SB + c16 * 8) * 2;
            CP_ASYNC16(dst, src);
        }
        CP_COMMIT();
        // W k-rows 128..255 (group B)
#pragma unroll
        for (int it = 0; it < 8; it++) {
            const int idx = it * NTHR + tid;
            const int row = 128 + (idx >> 5);
            const int c16 = idx & 31;
            const __half* src = whb + (size_t)row * DOUT + c16 * 8;
            const uint32_t dst = Ws_base + (uint32_t)(row * SB + c16 * 8) * 2;
            CP_ASYNC16(dst, src);
        }
        CP_COMMIT();
        // x(0) -> convert -> As[0] (own group rows)
#pragma unroll
        for (int it = 0; it < 2; it++) {
            const int idx = it * 128 + gtid;
            const int r = warp_m + (idx >> 3);
            const int c = (idx & 7) * 4;
            float4 v = *(const float4*)(xb + (size_t)r * (F_DIM * DIN) + c);
            *(uint2*)&As[r * SA + c] =
                make_uint2(pack_h2(v.x, v.y), pack_h2(v.z, v.w));
        }
        // x(1) in flight
#pragma unroll
        for (int it = 0; it < 2; it++) {
            const int idx = it * 128 + gtid;
            const int r = warp_m + (idx >> 3);
            const int c = (idx & 7) * 4;
            nx1[it] = *(const float4*)(xb + (size_t)r * (F_DIM * DIN) + KP + c);
        }
        CP_WAIT1();          // first W half ready
        __syncthreads();
    }

#pragma unroll
    for (int p = 0; p < 8; p++) {
        const int stage = p & 1;
        const bool more  = p < 7;
        const bool more2 = p < 6;

        // ---- x(p+2) LDG (distance 2) ----
        if (more2) {
            const int nk2 = (p + 2) * KP;
#pragma unroll
            for (int it = 0; it < 2; it++) {
                const int idx = it * 128 + gtid;
                const int r = warp_m + (idx >> 3);
                const int c = (idx & 7) * 4;
                nx2[it] = *(const float4*)(xb + (size_t)r * (F_DIM * DIN) + nk2 + c);
            }
        }

        // ---- MMAs for panel p ----
        uint32_t Ah[2][2][4];   // [mt][khalf]
        const uint32_t abase = a_addr0 + stage * AS_STAGE;
#pragma unroll
        for (int mt = 0; mt < 2; mt++) {
            LDSM4(Ah[mt][0], abase + mt * a_mtile);
            LDSM4(Ah[mt][1], abase + mt * a_mtile + a_khalf);
        }
        const uint32_t bbase = b_addr0 + p * b_kpanel;
#pragma unroll
        for (int nc = 0; nc < 4; nc++) {
            uint32_t B0[4], B1[4];
            const uint32_t ba = bbase + nc * 16 * 2;
            LDSM4T(B0, ba);
            LDSM4T(B1, ba + b_khalf);
#pragma unroll
            for (int mt = 0; mt < 2; mt++) {
#pragma unroll
                for (int nt = 0; nt < 2; nt++) {
                    float* c = acc[mt][nc * 2 + nt];
                    MMA16816F16(c, Ah[mt][0], B0[2*nt], B0[2*nt+1]);
                    MMA16816F16(c, Ah[mt][1], B1[2*nt], B1[2*nt+1]);
                }
            }
        }

        if (more) {
            // convert x(p+1) into alternate As stage (own group rows)
#pragma unroll
            for (int it = 0; it < 2; it++) {
                const int idx = it * 128 + gtid;
                const int r = warp_m + (idx >> 3);
                const int c = (idx & 7) * 4;
                *(uint2*)&As[(stage ^ 1) * (AS_STAGE / 2) + r * SA + c] =
                    make_uint2(pack_h2(nx1[it].x, nx1[it].y),
                               pack_h2(nx1[it].z, nx1[it].w));
            }
            if (p == 3) {
                CP_WAIT0();       // second W half ready (needed from panel 4)
                __syncthreads();
            } else {
                BAR_GRP(bar_id);  // group-scoped barrier only
            }
#pragma unroll
            for (int it = 0; it < 2; it++) nx1[it] = nx2[it];
        }
    }

    // ---- epilogue ----
    const int r_lane = lane >> 2;
    const int c_lane = (lane & 3) * 2;
#pragma unroll
    for (int mt = 0; mt < 2; mt++) {
#pragma unroll
        for (int nt = 0; nt < 8; nt++) {
            const int col = warp_n + nt * 8 + c_lane;
            const int row0 = mtile * MT + warp_m + mt * 16 + r_lane;
            float* o0 = out + (size_t)row0 * (F_DIM * DOUT) + (size_t)f * DOUT + col;
            *(float2*)o0 = make_float2(acc[mt][nt][0] + sbias[col],
                                       acc[mt][nt][1] + sbias[col + 1]);
            float* o1 = o0 + 8 * (F_DIM * DOUT);
            *(float2*)o1 = make_float2(acc[mt][nt][2] + sbias[col],
                                       acc[mt][nt][3] + sbias[col + 1]);
        }
    }
}

extern "C" void kernel_launch(void* const* d_in, const int* in_sizes, int n_in,
                              void* d_out, int out_size)
{
    const float* x = (n_in > 0) ? (const float*)d_in[0] : nullptr;
    const float* w = (n_in > 1) ? (const float*)d_in[1] : nullptr;
    const float* b = (n_in > 2) ? (const float*)d_in[2] : nullptr;
    for (int i = 0; i < n_in; i++) {
        if (in_sizes[i] == B_DIM * F_DIM * DIN)     x = (const float*)d_in[i];
        else if (in_sizes[i] == F_DIM * DIN * DOUT) w = (const float*)d_in[i];
        else if (in_sizes[i] == F_DIM * DOUT)       b = (const float*)d_in[i];
    }
    float* out = (float*)d_out;

    conv_w_kernel<<<4096, 256>>>(w);

    cudaFuncSetAttribute(nlinear_mma_kernel,
                         cudaFuncAttributeMaxDynamicSharedMemorySize, SMEM_TOTAL);
    nlinear_mma_kernel<<<dim3(B_DIM / MT, F_DIM), NTHR, SMEM_TOTAL>>>(x, b, out);
}